// round 11
// baseline (speedup 1.0000x reference)
#include <cuda_runtime.h>
#include <cuda_fp16.h>
#include <cstdint>

#define NN 50000
#define EE 640000
#define CC 128
#define SCAN_B 512

// ---------------- device scratch (no allocations allowed) ----------------
__device__ __half   g_hsrc[NN * CC];   // h_src (fp16 gather table)
__device__ float    g_skip[NN * CC];   // skip  = in @ Wl (fp32)
__device__ float    g_h   [NN * CC];   // layer-1 output
__device__ float    g_as  [NN];        // alpha_src per node
__device__ float    g_ad  [NN];        // alpha_dst per node
__device__ float    g_was1[CC], g_wad1[CC], g_was2[CC], g_wad2[CC];
__device__ __half   g_B1h[256 * 128];  // [n][k] fp16: rows 0-127 = Ws^T, 128-255 = Wl^T (layer 1)
__device__ __half   g_B2h[256 * 128];  // layer 2
// CSR (built once per launch; shared by both layers)
__device__ int      g_deg [NN];
__device__ int      g_off [NN + 1];
__device__ int      g_cur [NN];
__device__ int      g_bsum[128];
__device__ int      g_esrc[EE];        // src ids sorted by dst
__device__ int      g_edst[EE];        // dst ids in same order
__device__ float    g_ex  [EE];        // per-edge exp(logit), CSR order

// ---------------- combo (W@a vectors) + zero_deg merged ----------------
__global__ void combo_zero_kernel(const float* __restrict__ W1s, const float* __restrict__ a1s,
                                  const float* __restrict__ W1d, const float* __restrict__ a1d,
                                  const float* __restrict__ W2s, const float* __restrict__ a2s,
                                  const float* __restrict__ W2d, const float* __restrict__ a2d,
                                  int M) {
    int i = blockIdx.x * blockDim.x + threadIdx.x;
    if (i < M) g_deg[i] = 0;
    if (blockIdx.x == 0 && threadIdx.x < 128) {
        int k = threadIdx.x;
        float s1 = 0.f, d1 = 0.f, s2 = 0.f, d2 = 0.f;
        #pragma unroll 8
        for (int c = 0; c < CC; c++) {
            s1 += W1s[k * CC + c] * a1s[c];
            d1 += W1d[k * CC + c] * a1d[c];
            s2 += W2s[k * CC + c] * a2s[c];
            d2 += W2d[k * CC + c] * a2d[c];
        }
        g_was1[k] = s1; g_wad1[k] = d1; g_was2[k] = s2; g_wad2[k] = d2;
    }
}

// ---------------- CSR histogram + one-time B fp16 convert+transpose ([n][k]) ----------------
__global__ void hist_kernel(const int* __restrict__ dst,
                            const float* __restrict__ W1s, const float* __restrict__ Wl1,
                            const float* __restrict__ W2s, const float* __restrict__ Wl2,
                            int E) {
    int e = blockIdx.x * blockDim.x + threadIdx.x;
    if (e < E) atomicAdd(&g_deg[dst[e]], 1);
    if (e < 2 * 256 * 128) {
        int layer = e >> 15;           // 0 or 1
        int idx   = e & 32767;
        int n = idx >> 7, k = idx & 127;
        const float* Wp = layer ? ((n < 128) ? W2s : Wl2) : ((n < 128) ? W1s : Wl1);
        float v = __ldg(&Wp[k * 128 + (n & 127)]);
        (layer ? g_B2h : g_B1h)[n * 128 + k] = __float2half_rn(v);
    }
}
__global__ __launch_bounds__(SCAN_B) void scan1_kernel(int M) {
    __shared__ int wsum[16];
    int tid = threadIdx.x, lane = tid & 31, wid = tid >> 5;
    int i = blockIdx.x * SCAN_B + tid;
    int v = (i < M) ? g_deg[i] : 0;
    int x = v;
    #pragma unroll
    for (int o = 1; o < 32; o <<= 1) {
        int t = __shfl_up_sync(0xFFFFFFFFu, x, o);
        if (lane >= o) x += t;
    }
    if (lane == 31) wsum[wid] = x;
    __syncthreads();
    if (wid == 0) {
        int s = (lane < 16) ? wsum[lane] : 0;
        #pragma unroll
        for (int o = 1; o < 16; o <<= 1) {
            int t = __shfl_up_sync(0xFFFFFFFFu, s, o);
            if (lane >= o) s += t;
        }
        if (lane < 16) wsum[lane] = s;
    }
    __syncthreads();
    int base = wid ? wsum[wid - 1] : 0;
    int incl = base + x;
    if (i < M) g_off[i] = incl - v;
    if (tid == SCAN_B - 1) g_bsum[blockIdx.x] = incl;
}
__global__ __launch_bounds__(128) void scan2_kernel(int B) {
    __shared__ int sm[128];
    int v = (threadIdx.x < B) ? g_bsum[threadIdx.x] : 0;
    sm[threadIdx.x] = v;
    __syncthreads();
    for (int o = 1; o < 128; o <<= 1) {
        int t = (threadIdx.x >= o) ? sm[threadIdx.x - o] : 0;
        __syncthreads();
        sm[threadIdx.x] += t;
        __syncthreads();
    }
    if (threadIdx.x < B) g_bsum[threadIdx.x] = sm[threadIdx.x] - v;
}
__global__ void scan3_kernel(int M, int E) {
    int i = blockIdx.x * blockDim.x + threadIdx.x;
    if (i < M) {
        int o = g_off[i] + g_bsum[i / SCAN_B];
        g_off[i] = o;
        g_cur[i] = o;
    }
    if (i == 0) g_off[M] = E;
}
// scatter + fused layer-1 ex (g_as/g_ad already valid from GEMM layer 1)
__global__ void scatter_kernel(const int* __restrict__ src, const int* __restrict__ dst, int E) {
    int e = blockIdx.x * blockDim.x + threadIdx.x;
    if (e >= E) return;
    int s = src[e], d = dst[e];
    int pos = atomicAdd(&g_cur[d], 1);
    g_esrc[pos] = s;
    g_edst[pos] = d;
    float v = __ldg(&g_as[s]) + __ldg(&g_ad[d]);
    v = v > 0.f ? v : 0.2f * v;   // LeakyReLU(0.2)
    g_ex[pos] = __expf(v);
}

// ---------------- per-edge ex (layer 2), CSR order, coalesced ----------------
__global__ __launch_bounds__(256) void exf_kernel(int E) {
    int e = blockIdx.x * blockDim.x + threadIdx.x;
    if (e >= E) return;
    int s = g_esrc[e], d = g_edst[e];
    float v = __ldg(&g_as[s]) + __ldg(&g_ad[d]);
    v = v > 0.f ? v : 0.2f * v;
    g_ex[e] = __expf(v);
}

// ---------------- fused fp16 tensor-core GEMM (N=256: hsrc | skip) + alpha GEMV ----------------
// Round-9 mainloop (non-trans LDSM from Bs[n][k]); B staged by uint4 copy from
// pre-converted, pre-transposed g_Bh[n][k].
#define ASK 136
#define BSK 136
#define GSMEM ((128 * ASK + 256 * BSK) * 2 + 256 * 4)

#define LDSM4(r0, r1, r2, r3, addr)                                        \
    asm volatile("ldmatrix.sync.aligned.m8n8.x4.shared.b16 {%0,%1,%2,%3}, [%4];" \
                 : "=r"(r0), "=r"(r1), "=r"(r2), "=r"(r3) : "r"(addr))

__global__ __launch_bounds__(512) void gemm_fused_kernel(const float* __restrict__ A,
                                                         const __half* __restrict__ Bh,
                                                         const float* __restrict__ was,
                                                         const float* __restrict__ wad,
                                                         int M) {
    extern __shared__ __half smh[];
    __half* As = smh;                      // [128][ASK]   (m-major, k contiguous)
    __half* Bs = smh + 128 * ASK;          // [256][BSK]   (n-major, k contiguous)
    float* sWas = (float*)(smh + 128 * ASK + 256 * BSK);
    float* sWad = sWas + 128;

    const int tid  = threadIdx.x;
    const int row0 = blockIdx.x * 128;

    if (tid < 128) { sWas[tid] = was[tid]; sWad[tid] = wad[tid]; }
    __syncthreads();

    // ---- A staging (fp32 -> fp16) + fused fp32 alpha GEMV ----
    {
        int r  = tid >> 2;
        int kc = (tid & 3) * 32;
        int gr = row0 + r;
        float s = 0.f, dsum = 0.f;
        #pragma unroll
        for (int i = 0; i < 8; i++) {
            float4 v = (gr < M) ? *(const float4*)(A + (size_t)gr * 128 + kc + i * 4)
                                : make_float4(0.f, 0.f, 0.f, 0.f);
            float4 wsv = *(const float4*)(sWas + kc + i * 4);
            float4 wdv = *(const float4*)(sWad + kc + i * 4);
            s    += v.x * wsv.x + v.y * wsv.y + v.z * wsv.z + v.w * wsv.w;
            dsum += v.x * wdv.x + v.y * wdv.y + v.z * wdv.z + v.w * wdv.w;
            *(__half2*)(As + r * ASK + kc + i * 4)     = __float22half2_rn(make_float2(v.x, v.y));
            *(__half2*)(As + r * ASK + kc + i * 4 + 2) = __float22half2_rn(make_float2(v.z, v.w));
        }
        s    += __shfl_xor_sync(0xFFFFFFFFu, s, 1);
        s    += __shfl_xor_sync(0xFFFFFFFFu, s, 2);
        dsum += __shfl_xor_sync(0xFFFFFFFFu, dsum, 1);
        dsum += __shfl_xor_sync(0xFFFFFFFFu, dsum, 2);
        if ((tid & 3) == 0 && gr < M) { g_as[gr] = s; g_ad[gr] = dsum; }
    }

    // ---- B staging: straight uint4 copy gmem(fp16 [n][k]) -> Bs[n][k] ----
    {
        int n  = tid >> 1;                 // 0..255
        int c0 = (tid & 1) * 64;           // 64 halves = 8 uint4
        const uint4* s4 = (const uint4*)(Bh + n * 128 + c0);
        uint4* d4 = (uint4*)(Bs + n * BSK + c0);
        #pragma unroll
        for (int i = 0; i < 8; i++) d4[i] = __ldg(s4 + i);
    }
    __syncthreads();

    // ---- compute: warp tile 32 rows x 64 cols, K=128 via 8 x m16n8k16 ----
    const int w    = tid >> 5;
    const int lane = tid & 31;
    const int grp  = lane >> 2;
    const int tig  = lane & 3;
    const int wr0  = (w & 3) * 32;
    const int wn0  = (w >> 2) * 64;   // 0,64 -> hsrc ; 128,192 -> skip

    uint32_t a_addr[2], b_addr[4];
    {
        int arow = (lane & 15);
        int acol = (lane & 16) ? 8 : 0;
        #pragma unroll
        for (int mt = 0; mt < 2; mt++)
            a_addr[mt] = (uint32_t)__cvta_generic_to_shared(
                As + (wr0 + mt * 16 + arow) * ASK + acol);
        int brow = (lane & 7) + ((lane & 16) ? 8 : 0);
        int bcol = (lane & 8) ? 8 : 0;
        #pragma unroll
        for (int p = 0; p < 4; p++)
            b_addr[p] = (uint32_t)__cvta_generic_to_shared(
                Bs + (wn0 + p * 16 + brow) * BSK + bcol);
    }

    float acc[2][8][4];
    #pragma unroll
    for (int mt = 0; mt < 2; mt++)
        #pragma unroll
        for (int nt = 0; nt < 8; nt++)
            #pragma unroll
            for (int r = 0; r < 4; r++) acc[mt][nt][r] = 0.f;

    #pragma unroll
    for (int ks = 0; ks < 8; ks++) {
        uint32_t koff = ks * 32;   // 16 halves = 32 bytes
        uint32_t a[2][4];
        #pragma unroll
        for (int mt = 0; mt < 2; mt++)
            LDSM4(a[mt][0], a[mt][1], a[mt][2], a[mt][3], a_addr[mt] + koff);
        uint32_t b[8][2];
        #pragma unroll
        for (int p = 0; p < 4; p++)
            LDSM4(b[2 * p][0], b[2 * p][1], b[2 * p + 1][0], b[2 * p + 1][1],
                  b_addr[p] + koff);
        #pragma unroll
        for (int mt = 0; mt < 2; mt++)
            #pragma unroll
            for (int nt = 0; nt < 8; nt++) {
                float* d = acc[mt][nt];
                asm volatile(
                    "mma.sync.aligned.m16n8k16.row.col.f32.f16.f16.f32 "
                    "{%0,%1,%2,%3}, {%4,%5,%6,%7}, {%8,%9}, {%0,%1,%2,%3};"
                    : "+f"(d[0]), "+f"(d[1]), "+f"(d[2]), "+f"(d[3])
                    : "r"(a[mt][0]), "r"(a[mt][1]), "r"(a[mt][2]), "r"(a[mt][3]),
                      "r"(b[nt][0]), "r"(b[nt][1]));
            }
    }

    // ---- epilogue ----
    const bool to_h = (wn0 < 128);
    #pragma unroll
    for (int mt = 0; mt < 2; mt++) {
        int r_lo = row0 + wr0 + mt * 16 + grp;
        int r_hi = r_lo + 8;
        #pragma unroll
        for (int nt = 0; nt < 8; nt++) {
            int col = wn0 + nt * 8 + 2 * tig;
            if (to_h) {
                if (r_lo < M)
                    *(__half2*)(g_hsrc + (size_t)r_lo * 128 + col) =
                        __float22half2_rn(make_float2(acc[mt][nt][0], acc[mt][nt][1]));
                if (r_hi < M)
                    *(__half2*)(g_hsrc + (size_t)r_hi * 128 + col) =
                        __float22half2_rn(make_float2(acc[mt][nt][2], acc[mt][nt][3]));
            } else {
                int c2 = col - 128;
                if (r_lo < M)
                    *(float2*)(g_skip + (size_t)r_lo * 128 + c2) =
                        make_float2(acc[mt][nt][0], acc[mt][nt][1]);
                if (r_hi < M)
                    *(float2*)(g_skip + (size_t)r_hi * 128 + c2) =
                        make_float2(acc[mt][nt][2], acc[mt][nt][3]);
            }
        }
    }
}

// ---------------- fused aggregation + epilogue (WARP per node, 2x16-lane edge groups) ----------------
// Group g handles edges base+8g .. base+8g+7 -> 16 gathers in flight per node,
// one round for the typical degree. Groups merge via shfl_xor(16).
__global__ __launch_bounds__(256) void agg_kernel(const float* __restrict__ b,
                                                  const float* __restrict__ bl,
                                                  float* __restrict__ out_ext,
                                                  int relu_to_gh, int M) {
    int d = (blockIdx.x * blockDim.x + threadIdx.x) >> 5;
    int lane = threadIdx.x & 31;
    int g = lane >> 4;
    int l = lane & 15;
    if (d >= M) return;

    int o0 = g_off[d], o1 = g_off[d + 1];

    float accA[4] = {0.f, 0.f, 0.f, 0.f};
    float accB[4] = {0.f, 0.f, 0.f, 0.f};
    float Sp = 0.f;
    const __half* __restrict__ H = g_hsrc;

    for (int base = o0; base < o1; base += 16) {
        int b8 = base + g * 8;
        int   s_[8];
        float e_[8];
        #pragma unroll
        for (int u = 0; u < 8; u++) {
            int jj = b8 + u;
            bool ok = jj < o1;
            int idx = ok ? jj : o0;
            s_[u] = __ldg(&g_esrc[idx]);
            float ev = __ldg(&g_ex[idx]);
            e_[u] = ok ? ev : 0.f;
        }
        Sp += (e_[0] + e_[1]) + (e_[2] + e_[3]) + (e_[4] + e_[5]) + (e_[6] + e_[7]);
        uint4 u_[8];
        #pragma unroll
        for (int u = 0; u < 8; u++)
            u_[u] = *(const uint4*)(H + (size_t)s_[u] * 128 + l * 8);
        #pragma unroll
        for (int u = 0; u < 8; u++) {
            float2 f0 = __half22float2(*(__half2*)&u_[u].x);
            float2 f1 = __half22float2(*(__half2*)&u_[u].y);
            float2 f2 = __half22float2(*(__half2*)&u_[u].z);
            float2 f3 = __half22float2(*(__half2*)&u_[u].w);
            accA[0] += e_[u] * f0.x; accA[1] += e_[u] * f0.y;
            accA[2] += e_[u] * f1.x; accA[3] += e_[u] * f1.y;
            accB[0] += e_[u] * f2.x; accB[1] += e_[u] * f2.y;
            accB[2] += e_[u] * f3.x; accB[3] += e_[u] * f3.y;
        }
    }

    // merge the two 16-lane groups (lane l and l+16 hold the same columns)
    Sp += __shfl_xor_sync(0xFFFFFFFFu, Sp, 16);
    #pragma unroll
    for (int i = 0; i < 4; i++) {
        accA[i] += __shfl_xor_sync(0xFFFFFFFFu, accA[i], 16);
        accB[i] += __shfl_xor_sync(0xFFFFFFFFu, accB[i], 16);
    }
    float inv = 1.f / (Sp + 1e-16f);

    // lane (g=0,l) writes cols l*8..l*8+3 ; lane (g=1,l) writes cols l*8+4..l*8+7
    int col = l * 8 + g * 4;
    const float* accP = g ? accB : accA;
    float4 sk  = *(const float4*)(g_skip + (size_t)d * 128 + col);
    float4 bb  = *(const float4*)(b + col);
    float4 bb2 = *(const float4*)(bl + col);

    float4 o;
    o.x = accP[0] * inv + bb.x + sk.x + bb2.x;
    o.y = accP[1] * inv + bb.y + sk.y + bb2.y;
    o.z = accP[2] * inv + bb.z + sk.z + bb2.z;
    o.w = accP[3] * inv + bb.w + sk.w + bb2.w;

    if (relu_to_gh) {
        o.x = fmaxf(o.x, 0.f); o.y = fmaxf(o.y, 0.f);
        o.z = fmaxf(o.z, 0.f); o.w = fmaxf(o.w, 0.f);
        *(float4*)(g_h + (size_t)d * 128 + col) = o;
    } else {
        *(float4*)(out_ext + (size_t)d * 128 + col) = o;
    }
}

// ---------------- launch ----------------
extern "C" void kernel_launch(void* const* d_in, const int* in_sizes, int n_in,
                              void* d_out, int out_size) {
    const float* x   = (const float*)d_in[0];
    const int*   ei  = (const int*)  d_in[1];
    const float* W1s = (const float*)d_in[2];
    const float* W1d = (const float*)d_in[3];
    const float* a1s = (const float*)d_in[4];
    const float* a1d = (const float*)d_in[5];
    const float* b1  = (const float*)d_in[6];
    const float* Wl1 = (const float*)d_in[7];
    const float* bl1 = (const float*)d_in[8];
    const float* W2s = (const float*)d_in[9];
    const float* W2d = (const float*)d_in[10];
    const float* a2s = (const float*)d_in[11];
    const float* a2d = (const float*)d_in[12];
    const float* b2  = (const float*)d_in[13];
    const float* Wl2 = (const float*)d_in[14];
    const float* bl2 = (const float*)d_in[15];

    const int M = in_sizes[0] / CC;        // 50000
    const int E = in_sizes[1] / 2;         // 640000
    const int* src = ei;
    const int* dst = ei + E;

    float *p_h = nullptr, *p_was1 = nullptr, *p_wad1 = nullptr,
          *p_was2 = nullptr, *p_wad2 = nullptr;
    __half *p_B1h = nullptr, *p_B2h = nullptr;
    cudaGetSymbolAddress((void**)&p_h,    g_h);     // queries only, capture-safe
    cudaGetSymbolAddress((void**)&p_was1, g_was1);
    cudaGetSymbolAddress((void**)&p_wad1, g_wad1);
    cudaGetSymbolAddress((void**)&p_was2, g_was2);
    cudaGetSymbolAddress((void**)&p_wad2, g_wad2);
    cudaGetSymbolAddress((void**)&p_B1h,  g_B1h);
    cudaGetSymbolAddress((void**)&p_B2h,  g_B2h);

    static bool attr_set = false;
    if (!attr_set) {
        cudaFuncSetAttribute(gemm_fused_kernel,
                             cudaFuncAttributeMaxDynamicSharedMemorySize, GSMEM);
        attr_set = true;
    }

    const int nodeBlocks = (M + 255) / 256;
    const int edgeBlocks = (E + 255) / 256;
    const int warpBlocks = (int)(((long long)M * 32 + 255) / 256);
    const int scanBlocks = (M + SCAN_B - 1) / SCAN_B;
    const int gemmGrid   = (M + 127) / 128;

    combo_zero_kernel<<<nodeBlocks, 256>>>(W1s, a1s, W1d, a1d, W2s, a2s, W2d, a2d, M);  // 1
    hist_kernel<<<edgeBlocks, 256>>>(dst, W1s, Wl1, W2s, Wl2, E);                       // 2
    scan1_kernel<<<scanBlocks, SCAN_B>>>(M);                                            // 3
    gemm_fused_kernel<<<gemmGrid, 512, GSMEM>>>(x, p_B1h, p_was1, p_wad1, M);           // 4 (ncu window)
    scan2_kernel<<<1, 128>>>(scanBlocks);                                               // 5
    scan3_kernel<<<nodeBlocks, 256>>>(M, E);                                            // 6
    scatter_kernel<<<edgeBlocks, 256>>>(src, dst, E);                                   // 7 (+ layer-1 ex)

    // ---- layer 1 ----
    agg_kernel<<<warpBlocks, 256>>>(b1, bl1, nullptr, 1, M);                            // 8

    // ---- layer 2 ----
    gemm_fused_kernel<<<gemmGrid, 512, GSMEM>>>(p_h, p_B2h, p_was2, p_wad2, M);         // 9
    exf_kernel<<<edgeBlocks, 256>>>(E);                                                 // 10
    agg_kernel<<<warpBlocks, 256>>>(b2, bl2, (float*)d_out, 0, M);                      // 11
}

// round 12
// speedup vs baseline: 1.0085x; 1.0085x over previous
#include <cuda_runtime.h>
#include <cuda_fp16.h>
#include <cstdint>

#define NN 50000
#define EE 640000
#define CC 128
#define SCAN_B 512

// ---------------- device scratch (no allocations allowed) ----------------
__device__ __half   g_hsrc[NN * CC];   // h_src (fp16 gather table)
__device__ float    g_skip[NN * CC];   // skip  = in @ Wl (fp32)
__device__ float    g_h   [NN * CC];   // layer-1 output
__device__ float    g_as  [NN];        // alpha_src per node
__device__ float    g_ad  [NN];        // alpha_dst per node
__device__ float    g_was1[CC], g_wad1[CC], g_was2[CC], g_wad2[CC];
__device__ __half   g_B1h[256 * 128];  // [n][k] fp16: rows 0-127 = Ws^T, 128-255 = Wl^T (layer 1)
__device__ __half   g_B2h[256 * 128];  // layer 2
// CSR (built once per launch; shared by both layers)
__device__ int      g_deg [NN];
__device__ int      g_off [NN + 1];
__device__ int      g_cur [NN];
__device__ int      g_bsum[128];
__device__ int      g_esrc[EE];        // src ids sorted by dst
__device__ int      g_edst[EE];        // dst ids in same order
__device__ float    g_ex  [EE];        // per-edge exp(logit), CSR order

// ---------------- combo (W@a vectors) + zero_deg merged ----------------
__global__ void combo_zero_kernel(const float* __restrict__ W1s, const float* __restrict__ a1s,
                                  const float* __restrict__ W1d, const float* __restrict__ a1d,
                                  const float* __restrict__ W2s, const float* __restrict__ a2s,
                                  const float* __restrict__ W2d, const float* __restrict__ a2d,
                                  int M) {
    int i = blockIdx.x * blockDim.x + threadIdx.x;
    if (i < M) g_deg[i] = 0;
    if (blockIdx.x == 0 && threadIdx.x < 128) {
        int k = threadIdx.x;
        float s1 = 0.f, d1 = 0.f, s2 = 0.f, d2 = 0.f;
        #pragma unroll 8
        for (int c = 0; c < CC; c++) {
            s1 += W1s[k * CC + c] * a1s[c];
            d1 += W1d[k * CC + c] * a1d[c];
            s2 += W2s[k * CC + c] * a2s[c];
            d2 += W2d[k * CC + c] * a2d[c];
        }
        g_was1[k] = s1; g_wad1[k] = d1; g_was2[k] = s2; g_wad2[k] = d2;
    }
}

// ---------------- CSR histogram + one-time B fp16 convert+transpose ([n][k]) ----------------
__global__ void hist_kernel(const int* __restrict__ dst,
                            const float* __restrict__ W1s, const float* __restrict__ Wl1,
                            const float* __restrict__ W2s, const float* __restrict__ Wl2,
                            int E) {
    int e = blockIdx.x * blockDim.x + threadIdx.x;
    if (e < E) atomicAdd(&g_deg[dst[e]], 1);
    if (e < 2 * 256 * 128) {
        int layer = e >> 15;           // 0 or 1
        int idx   = e & 32767;
        int n = idx >> 7, k = idx & 127;
        const float* Wp = layer ? ((n < 128) ? W2s : Wl2) : ((n < 128) ? W1s : Wl1);
        float v = __ldg(&Wp[k * 128 + (n & 127)]);
        (layer ? g_B2h : g_B1h)[n * 128 + k] = __float2half_rn(v);
    }
}
__global__ __launch_bounds__(SCAN_B) void scan1_kernel(int M) {
    __shared__ int wsum[16];
    int tid = threadIdx.x, lane = tid & 31, wid = tid >> 5;
    int i = blockIdx.x * SCAN_B + tid;
    int v = (i < M) ? g_deg[i] : 0;
    int x = v;
    #pragma unroll
    for (int o = 1; o < 32; o <<= 1) {
        int t = __shfl_up_sync(0xFFFFFFFFu, x, o);
        if (lane >= o) x += t;
    }
    if (lane == 31) wsum[wid] = x;
    __syncthreads();
    if (wid == 0) {
        int s = (lane < 16) ? wsum[lane] : 0;
        #pragma unroll
        for (int o = 1; o < 16; o <<= 1) {
            int t = __shfl_up_sync(0xFFFFFFFFu, s, o);
            if (lane >= o) s += t;
        }
        if (lane < 16) wsum[lane] = s;
    }
    __syncthreads();
    int base = wid ? wsum[wid - 1] : 0;
    int incl = base + x;
    if (i < M) g_off[i] = incl - v;
    if (tid == SCAN_B - 1) g_bsum[blockIdx.x] = incl;
}
__global__ __launch_bounds__(128) void scan2_kernel(int B) {
    __shared__ int sm[128];
    int v = (threadIdx.x < B) ? g_bsum[threadIdx.x] : 0;
    sm[threadIdx.x] = v;
    __syncthreads();
    for (int o = 1; o < 128; o <<= 1) {
        int t = (threadIdx.x >= o) ? sm[threadIdx.x - o] : 0;
        __syncthreads();
        sm[threadIdx.x] += t;
        __syncthreads();
    }
    if (threadIdx.x < B) g_bsum[threadIdx.x] = sm[threadIdx.x] - v;
}
__global__ void scan3_kernel(int M, int E) {
    int i = blockIdx.x * blockDim.x + threadIdx.x;
    if (i < M) {
        int o = g_off[i] + g_bsum[i / SCAN_B];
        g_off[i] = o;
        g_cur[i] = o;
    }
    if (i == 0) g_off[M] = E;
}
// scatter + fused layer-1 ex (g_as/g_ad already valid from GEMM layer 1)
__global__ void scatter_kernel(const int* __restrict__ src, const int* __restrict__ dst, int E) {
    int e = blockIdx.x * blockDim.x + threadIdx.x;
    if (e >= E) return;
    int s = src[e], d = dst[e];
    int pos = atomicAdd(&g_cur[d], 1);
    g_esrc[pos] = s;
    g_edst[pos] = d;
    float v = __ldg(&g_as[s]) + __ldg(&g_ad[d]);
    v = v > 0.f ? v : 0.2f * v;   // LeakyReLU(0.2)
    g_ex[pos] = __expf(v);
}

// ---------------- per-edge ex (layer 2), CSR order, coalesced ----------------
__global__ __launch_bounds__(256) void exf_kernel(int E) {
    int e = blockIdx.x * blockDim.x + threadIdx.x;
    if (e >= E) return;
    int s = g_esrc[e], d = g_edst[e];
    float v = __ldg(&g_as[s]) + __ldg(&g_ad[d]);
    v = v > 0.f ? v : 0.2f * v;
    g_ex[e] = __expf(v);
}

// ---------------- fused fp16 tensor-core GEMM (N=256: hsrc | skip) + alpha GEMV ----------------
// Round-9 mainloop (non-trans LDSM from Bs[n][k]); B staged by uint4 copy from
// pre-converted, pre-transposed g_Bh[n][k].
#define ASK 136
#define BSK 136
#define GSMEM ((128 * ASK + 256 * BSK) * 2 + 256 * 4)

#define LDSM4(r0, r1, r2, r3, addr)                                        \
    asm volatile("ldmatrix.sync.aligned.m8n8.x4.shared.b16 {%0,%1,%2,%3}, [%4];" \
                 : "=r"(r0), "=r"(r1), "=r"(r2), "=r"(r3) : "r"(addr))

__global__ __launch_bounds__(512) void gemm_fused_kernel(const float* __restrict__ A,
                                                         const __half* __restrict__ Bh,
                                                         const float* __restrict__ was,
                                                         const float* __restrict__ wad,
                                                         int M) {
    extern __shared__ __half smh[];
    __half* As = smh;                      // [128][ASK]   (m-major, k contiguous)
    __half* Bs = smh + 128 * ASK;          // [256][BSK]   (n-major, k contiguous)
    float* sWas = (float*)(smh + 128 * ASK + 256 * BSK);
    float* sWad = sWas + 128;

    const int tid  = threadIdx.x;
    const int row0 = blockIdx.x * 128;

    if (tid < 128) { sWas[tid] = was[tid]; sWad[tid] = wad[tid]; }
    __syncthreads();

    // ---- A staging (fp32 -> fp16) + fused fp32 alpha GEMV ----
    {
        int r  = tid >> 2;
        int kc = (tid & 3) * 32;
        int gr = row0 + r;
        float s = 0.f, dsum = 0.f;
        #pragma unroll
        for (int i = 0; i < 8; i++) {
            float4 v = (gr < M) ? *(const float4*)(A + (size_t)gr * 128 + kc + i * 4)
                                : make_float4(0.f, 0.f, 0.f, 0.f);
            float4 wsv = *(const float4*)(sWas + kc + i * 4);
            float4 wdv = *(const float4*)(sWad + kc + i * 4);
            s    += v.x * wsv.x + v.y * wsv.y + v.z * wsv.z + v.w * wsv.w;
            dsum += v.x * wdv.x + v.y * wdv.y + v.z * wdv.z + v.w * wdv.w;
            *(__half2*)(As + r * ASK + kc + i * 4)     = __float22half2_rn(make_float2(v.x, v.y));
            *(__half2*)(As + r * ASK + kc + i * 4 + 2) = __float22half2_rn(make_float2(v.z, v.w));
        }
        s    += __shfl_xor_sync(0xFFFFFFFFu, s, 1);
        s    += __shfl_xor_sync(0xFFFFFFFFu, s, 2);
        dsum += __shfl_xor_sync(0xFFFFFFFFu, dsum, 1);
        dsum += __shfl_xor_sync(0xFFFFFFFFu, dsum, 2);
        if ((tid & 3) == 0 && gr < M) { g_as[gr] = s; g_ad[gr] = dsum; }
    }

    // ---- B staging: straight uint4 copy gmem(fp16 [n][k]) -> Bs[n][k] ----
    {
        int n  = tid >> 1;                 // 0..255
        int c0 = (tid & 1) * 64;           // 64 halves = 8 uint4
        const uint4* s4 = (const uint4*)(Bh + n * 128 + c0);
        uint4* d4 = (uint4*)(Bs + n * BSK + c0);
        #pragma unroll
        for (int i = 0; i < 8; i++) d4[i] = __ldg(s4 + i);
    }
    __syncthreads();

    // ---- compute: warp tile 32 rows x 64 cols, K=128 via 8 x m16n8k16 ----
    const int w    = tid >> 5;
    const int lane = tid & 31;
    const int grp  = lane >> 2;
    const int tig  = lane & 3;
    const int wr0  = (w & 3) * 32;
    const int wn0  = (w >> 2) * 64;   // 0,64 -> hsrc ; 128,192 -> skip

    uint32_t a_addr[2], b_addr[4];
    {
        int arow = (lane & 15);
        int acol = (lane & 16) ? 8 : 0;
        #pragma unroll
        for (int mt = 0; mt < 2; mt++)
            a_addr[mt] = (uint32_t)__cvta_generic_to_shared(
                As + (wr0 + mt * 16 + arow) * ASK + acol);
        int brow = (lane & 7) + ((lane & 16) ? 8 : 0);
        int bcol = (lane & 8) ? 8 : 0;
        #pragma unroll
        for (int p = 0; p < 4; p++)
            b_addr[p] = (uint32_t)__cvta_generic_to_shared(
                Bs + (wn0 + p * 16 + brow) * BSK + bcol);
    }

    float acc[2][8][4];
    #pragma unroll
    for (int mt = 0; mt < 2; mt++)
        #pragma unroll
        for (int nt = 0; nt < 8; nt++)
            #pragma unroll
            for (int r = 0; r < 4; r++) acc[mt][nt][r] = 0.f;

    #pragma unroll
    for (int ks = 0; ks < 8; ks++) {
        uint32_t koff = ks * 32;   // 16 halves = 32 bytes
        uint32_t a[2][4];
        #pragma unroll
        for (int mt = 0; mt < 2; mt++)
            LDSM4(a[mt][0], a[mt][1], a[mt][2], a[mt][3], a_addr[mt] + koff);
        uint32_t b[8][2];
        #pragma unroll
        for (int p = 0; p < 4; p++)
            LDSM4(b[2 * p][0], b[2 * p][1], b[2 * p + 1][0], b[2 * p + 1][1],
                  b_addr[p] + koff);
        #pragma unroll
        for (int mt = 0; mt < 2; mt++)
            #pragma unroll
            for (int nt = 0; nt < 8; nt++) {
                float* d = acc[mt][nt];
                asm volatile(
                    "mma.sync.aligned.m16n8k16.row.col.f32.f16.f16.f32 "
                    "{%0,%1,%2,%3}, {%4,%5,%6,%7}, {%8,%9}, {%0,%1,%2,%3};"
                    : "+f"(d[0]), "+f"(d[1]), "+f"(d[2]), "+f"(d[3])
                    : "r"(a[mt][0]), "r"(a[mt][1]), "r"(a[mt][2]), "r"(a[mt][3]),
                      "r"(b[nt][0]), "r"(b[nt][1]));
            }
    }

    // ---- epilogue ----
    const bool to_h = (wn0 < 128);
    #pragma unroll
    for (int mt = 0; mt < 2; mt++) {
        int r_lo = row0 + wr0 + mt * 16 + grp;
        int r_hi = r_lo + 8;
        #pragma unroll
        for (int nt = 0; nt < 8; nt++) {
            int col = wn0 + nt * 8 + 2 * tig;
            if (to_h) {
                if (r_lo < M)
                    *(__half2*)(g_hsrc + (size_t)r_lo * 128 + col) =
                        __float22half2_rn(make_float2(acc[mt][nt][0], acc[mt][nt][1]));
                if (r_hi < M)
                    *(__half2*)(g_hsrc + (size_t)r_hi * 128 + col) =
                        __float22half2_rn(make_float2(acc[mt][nt][2], acc[mt][nt][3]));
            } else {
                int c2 = col - 128;
                if (r_lo < M)
                    *(float2*)(g_skip + (size_t)r_lo * 128 + c2) =
                        make_float2(acc[mt][nt][0], acc[mt][nt][1]);
                if (r_hi < M)
                    *(float2*)(g_skip + (size_t)r_hi * 128 + c2) =
                        make_float2(acc[mt][nt][2], acc[mt][nt][3]);
            }
        }
    }
}

// ---------------- fused aggregation + epilogue (WARP per node, 2x16-lane edge groups) ----------------
// Group g handles edges base+8g .. base+8g+7 -> 16 gathers in flight per node,
// one round for the typical degree. Groups merge via shfl_xor(16).
__global__ __launch_bounds__(256) void agg_kernel(const float* __restrict__ b,
                                                  const float* __restrict__ bl,
                                                  float* __restrict__ out_ext,
                                                  int relu_to_gh, int M) {
    int d = (blockIdx.x * blockDim.x + threadIdx.x) >> 5;
    int lane = threadIdx.x & 31;
    int g = lane >> 4;
    int l = lane & 15;
    if (d >= M) return;

    int o0 = g_off[d], o1 = g_off[d + 1];

    float accA[4] = {0.f, 0.f, 0.f, 0.f};
    float accB[4] = {0.f, 0.f, 0.f, 0.f};
    float Sp = 0.f;
    const __half* __restrict__ H = g_hsrc;

    for (int base = o0; base < o1; base += 16) {
        int b8 = base + g * 8;
        int   s_[8];
        float e_[8];
        #pragma unroll
        for (int u = 0; u < 8; u++) {
            int jj = b8 + u;
            bool ok = jj < o1;
            int idx = ok ? jj : o0;
            s_[u] = __ldg(&g_esrc[idx]);
            float ev = __ldg(&g_ex[idx]);
            e_[u] = ok ? ev : 0.f;
        }
        Sp += (e_[0] + e_[1]) + (e_[2] + e_[3]) + (e_[4] + e_[5]) + (e_[6] + e_[7]);
        uint4 u_[8];
        #pragma unroll
        for (int u = 0; u < 8; u++)
            u_[u] = *(const uint4*)(H + (size_t)s_[u] * 128 + l * 8);
        #pragma unroll
        for (int u = 0; u < 8; u++) {
            float2 f0 = __half22float2(*(__half2*)&u_[u].x);
            float2 f1 = __half22float2(*(__half2*)&u_[u].y);
            float2 f2 = __half22float2(*(__half2*)&u_[u].z);
            float2 f3 = __half22float2(*(__half2*)&u_[u].w);
            accA[0] += e_[u] * f0.x; accA[1] += e_[u] * f0.y;
            accA[2] += e_[u] * f1.x; accA[3] += e_[u] * f1.y;
            accB[0] += e_[u] * f2.x; accB[1] += e_[u] * f2.y;
            accB[2] += e_[u] * f3.x; accB[3] += e_[u] * f3.y;
        }
    }

    // merge the two 16-lane groups (lane l and l+16 hold the same columns)
    Sp += __shfl_xor_sync(0xFFFFFFFFu, Sp, 16);
    #pragma unroll
    for (int i = 0; i < 4; i++) {
        accA[i] += __shfl_xor_sync(0xFFFFFFFFu, accA[i], 16);
        accB[i] += __shfl_xor_sync(0xFFFFFFFFu, accB[i], 16);
    }
    float inv = 1.f / (Sp + 1e-16f);

    // lane (g=0,l) writes cols l*8..l*8+3 ; lane (g=1,l) writes cols l*8+4..l*8+7
    int col = l * 8 + g * 4;
    const float* accP = g ? accB : accA;
    float4 sk  = *(const float4*)(g_skip + (size_t)d * 128 + col);
    float4 bb  = *(const float4*)(b + col);
    float4 bb2 = *(const float4*)(bl + col);

    float4 o;
    o.x = accP[0] * inv + bb.x + sk.x + bb2.x;
    o.y = accP[1] * inv + bb.y + sk.y + bb2.y;
    o.z = accP[2] * inv + bb.z + sk.z + bb2.z;
    o.w = accP[3] * inv + bb.w + sk.w + bb2.w;

    if (relu_to_gh) {
        o.x = fmaxf(o.x, 0.f); o.y = fmaxf(o.y, 0.f);
        o.z = fmaxf(o.z, 0.f); o.w = fmaxf(o.w, 0.f);
        *(float4*)(g_h + (size_t)d * 128 + col) = o;
    } else {
        *(float4*)(out_ext + (size_t)d * 128 + col) = o;
    }
}

// ---------------- launch ----------------
extern "C" void kernel_launch(void* const* d_in, const int* in_sizes, int n_in,
                              void* d_out, int out_size) {
    const float* x   = (const float*)d_in[0];
    const int*   ei  = (const int*)  d_in[1];
    const float* W1s = (const float*)d_in[2];
    const float* W1d = (const float*)d_in[3];
    const float* a1s = (const float*)d_in[4];
    const float* a1d = (const float*)d_in[5];
    const float* b1  = (const float*)d_in[6];
    const float* Wl1 = (const float*)d_in[7];
    const float* bl1 = (const float*)d_in[8];
    const float* W2s = (const float*)d_in[9];
    const float* W2d = (const float*)d_in[10];
    const float* a2s = (const float*)d_in[11];
    const float* a2d = (const float*)d_in[12];
    const float* b2  = (const float*)d_in[13];
    const float* Wl2 = (const float*)d_in[14];
    const float* bl2 = (const float*)d_in[15];

    const int M = in_sizes[0] / CC;        // 50000
    const int E = in_sizes[1] / 2;         // 640000
    const int* src = ei;
    const int* dst = ei + E;

    float *p_h = nullptr, *p_was1 = nullptr, *p_wad1 = nullptr,
          *p_was2 = nullptr, *p_wad2 = nullptr;
    __half *p_B1h = nullptr, *p_B2h = nullptr;
    cudaGetSymbolAddress((void**)&p_h,    g_h);     // queries only, capture-safe
    cudaGetSymbolAddress((void**)&p_was1, g_was1);
    cudaGetSymbolAddress((void**)&p_wad1, g_wad1);
    cudaGetSymbolAddress((void**)&p_was2, g_was2);
    cudaGetSymbolAddress((void**)&p_wad2, g_wad2);
    cudaGetSymbolAddress((void**)&p_B1h,  g_B1h);
    cudaGetSymbolAddress((void**)&p_B2h,  g_B2h);

    static bool attr_set = false;
    if (!attr_set) {
        cudaFuncSetAttribute(gemm_fused_kernel,
                             cudaFuncAttributeMaxDynamicSharedMemorySize, GSMEM);
        attr_set = true;
    }

    const int nodeBlocks = (M + 255) / 256;
    const int edgeBlocks = (E + 255) / 256;
    const int warpBlocks = (int)(((long long)M * 32 + 255) / 256);
    const int scanBlocks = (M + SCAN_B - 1) / SCAN_B;
    const int gemmGrid   = (M + 127) / 128;

    combo_zero_kernel<<<nodeBlocks, 256>>>(W1s, a1s, W1d, a1d, W2s, a2s, W2d, a2d, M);  // 1
    hist_kernel<<<edgeBlocks, 256>>>(dst, W1s, Wl1, W2s, Wl2, E);                       // 2
    scan1_kernel<<<scanBlocks, SCAN_B>>>(M);                                            // 3
    gemm_fused_kernel<<<gemmGrid, 512, GSMEM>>>(x, p_B1h, p_was1, p_wad1, M);           // 4 (ncu window)
    scan2_kernel<<<1, 128>>>(scanBlocks);                                               // 5
    scan3_kernel<<<nodeBlocks, 256>>>(M, E);                                            // 6
    scatter_kernel<<<edgeBlocks, 256>>>(src, dst, E);                                   // 7 (+ layer-1 ex)

    // ---- layer 1 ----
    agg_kernel<<<warpBlocks, 256>>>(b1, bl1, nullptr, 1, M);                            // 8

    // ---- layer 2 ----
    gemm_fused_kernel<<<gemmGrid, 512, GSMEM>>>(p_h, p_B2h, p_was2, p_wad2, M);         // 9
    exf_kernel<<<edgeBlocks, 256>>>(E);                                                 // 10
    agg_kernel<<<warpBlocks, 256>>>(b2, bl2, (float*)d_out, 0, M);                      // 11
}

// round 13
// speedup vs baseline: 1.0753x; 1.0662x over previous
#include <cuda_runtime.h>
#include <cuda_fp16.h>
#include <cstdint>

#define NN 50000
#define EE 640000
#define CC 128
#define SCAN_B 512

// ---------------- device scratch (no allocations allowed) ----------------
__device__ __half   g_hsrc[NN * CC];   // h_src (fp16 gather table)
__device__ __half   g_skip[NN * CC];   // skip  = in @ Wl (fp16)
__device__ float    g_h   [NN * CC];   // layer-1 output
__device__ float    g_as  [NN];        // alpha_src per node
__device__ float    g_ad  [NN];        // alpha_dst per node
__device__ float    g_was1[CC], g_wad1[CC], g_was2[CC], g_wad2[CC];
// CSR (built once per launch; shared by both layers)
__device__ int      g_deg [NN];
__device__ int      g_off [NN + 1];
__device__ int      g_cur [NN];
__device__ int      g_bsum[128];
__device__ int      g_esrc[EE];        // src ids sorted by dst
__device__ int      g_edst[EE];        // dst ids in same order
__device__ float    g_ex  [EE];        // per-edge exp(logit), CSR order

// ---------------- combo (W@a vectors) + zero_deg merged ----------------
__global__ void combo_zero_kernel(const float* __restrict__ W1s, const float* __restrict__ a1s,
                                  const float* __restrict__ W1d, const float* __restrict__ a1d,
                                  const float* __restrict__ W2s, const float* __restrict__ a2s,
                                  const float* __restrict__ W2d, const float* __restrict__ a2d,
                                  int M) {
    int i = blockIdx.x * blockDim.x + threadIdx.x;
    if (i < M) g_deg[i] = 0;
    if (blockIdx.x == 0 && threadIdx.x < 128) {
        int k = threadIdx.x;
        float s1 = 0.f, d1 = 0.f, s2 = 0.f, d2 = 0.f;
        #pragma unroll 8
        for (int c = 0; c < CC; c++) {
            s1 += W1s[k * CC + c] * a1s[c];
            d1 += W1d[k * CC + c] * a1d[c];
            s2 += W2s[k * CC + c] * a2s[c];
            d2 += W2d[k * CC + c] * a2d[c];
        }
        g_was1[k] = s1; g_wad1[k] = d1; g_was2[k] = s2; g_wad2[k] = d2;
    }
}

// ---------------- CSR build ----------------
__global__ void hist_kernel(const int* __restrict__ dst, int E) {
    int e = blockIdx.x * blockDim.x + threadIdx.x;
    if (e < E) atomicAdd(&g_deg[dst[e]], 1);
}
__global__ __launch_bounds__(SCAN_B) void scan1_kernel(int M) {
    __shared__ int wsum[16];
    int tid = threadIdx.x, lane = tid & 31, wid = tid >> 5;
    int i = blockIdx.x * SCAN_B + tid;
    int v = (i < M) ? g_deg[i] : 0;
    int x = v;
    #pragma unroll
    for (int o = 1; o < 32; o <<= 1) {
        int t = __shfl_up_sync(0xFFFFFFFFu, x, o);
        if (lane >= o) x += t;
    }
    if (lane == 31) wsum[wid] = x;
    __syncthreads();
    if (wid == 0) {
        int s = (lane < 16) ? wsum[lane] : 0;
        #pragma unroll
        for (int o = 1; o < 16; o <<= 1) {
            int t = __shfl_up_sync(0xFFFFFFFFu, s, o);
            if (lane >= o) s += t;
        }
        if (lane < 16) wsum[lane] = s;
    }
    __syncthreads();
    int base = wid ? wsum[wid - 1] : 0;
    int incl = base + x;
    if (i < M) g_off[i] = incl - v;
    if (tid == SCAN_B - 1) g_bsum[blockIdx.x] = incl;
}
__global__ __launch_bounds__(128) void scan2_kernel(int B) {
    __shared__ int sm[128];
    int v = (threadIdx.x < B) ? g_bsum[threadIdx.x] : 0;
    sm[threadIdx.x] = v;
    __syncthreads();
    for (int o = 1; o < 128; o <<= 1) {
        int t = (threadIdx.x >= o) ? sm[threadIdx.x - o] : 0;
        __syncthreads();
        sm[threadIdx.x] += t;
        __syncthreads();
    }
    if (threadIdx.x < B) g_bsum[threadIdx.x] = sm[threadIdx.x] - v;
}
__global__ void scan3_kernel(int M, int E) {
    int i = blockIdx.x * blockDim.x + threadIdx.x;
    if (i < M) {
        int o = g_off[i] + g_bsum[i / SCAN_B];
        g_off[i] = o;
        g_cur[i] = o;
    }
    if (i == 0) g_off[M] = E;
}
__global__ void scatter_kernel(const int* __restrict__ src, const int* __restrict__ dst, int E) {
    int e = blockIdx.x * blockDim.x + threadIdx.x;
    if (e >= E) return;
    int d = dst[e];
    int pos = atomicAdd(&g_cur[d], 1);
    g_esrc[pos] = src[e];
    g_edst[pos] = d;
}

// ---------------- per-edge ex = exp(leaky(as[s]+ad[d])), CSR order, coalesced ----------------
__global__ __launch_bounds__(256) void exf_kernel(int E) {
    int e = blockIdx.x * blockDim.x + threadIdx.x;
    if (e >= E) return;
    int s = g_esrc[e], d = g_edst[e];
    float v = __ldg(&g_as[s]) + __ldg(&g_ad[d]);
    v = v > 0.f ? v : 0.2f * v;   // LeakyReLU(0.2)
    g_ex[e] = __expf(v);
}

// ---------------- fused fp16 tensor-core GEMM (N=256: hsrc | skip) + alpha GEMV ----------------
// Round-9 structure exactly; only the skip epilogue is now fp16.
#define ASK 136
#define BSK 136
#define GSMEM ((128 * ASK + 256 * BSK) * 2 + 256 * 4)

#define LDSM4(r0, r1, r2, r3, addr)                                        \
    asm volatile("ldmatrix.sync.aligned.m8n8.x4.shared.b16 {%0,%1,%2,%3}, [%4];" \
                 : "=r"(r0), "=r"(r1), "=r"(r2), "=r"(r3) : "r"(addr))

__global__ __launch_bounds__(512) void gemm_fused_kernel(const float* __restrict__ A,
                                                         const float* __restrict__ B0,
                                                         const float* __restrict__ B1,
                                                         const float* __restrict__ was,
                                                         const float* __restrict__ wad,
                                                         int M) {
    extern __shared__ __half smh[];
    __half* As = smh;                      // [128][ASK]   (m-major, k contiguous)
    __half* Bs = smh + 128 * ASK;          // [256][BSK]   (n-major, k contiguous)
    float* sWas = (float*)(smh + 128 * ASK + 256 * BSK);
    float* sWad = sWas + 128;

    const int tid  = threadIdx.x;
    const int row0 = blockIdx.x * 128;

    if (tid < 128) { sWas[tid] = was[tid]; sWad[tid] = wad[tid]; }
    __syncthreads();

    // ---- A staging (fp32 -> fp16) + fused fp32 alpha GEMV ----
    {
        int r  = tid >> 2;
        int kc = (tid & 3) * 32;
        int gr = row0 + r;
        float s = 0.f, dsum = 0.f;
        #pragma unroll
        for (int i = 0; i < 8; i++) {
            float4 v = (gr < M) ? *(const float4*)(A + (size_t)gr * 128 + kc + i * 4)
                                : make_float4(0.f, 0.f, 0.f, 0.f);
            float4 wsv = *(const float4*)(sWas + kc + i * 4);
            float4 wdv = *(const float4*)(sWad + kc + i * 4);
            s    += v.x * wsv.x + v.y * wsv.y + v.z * wsv.z + v.w * wsv.w;
            dsum += v.x * wdv.x + v.y * wdv.y + v.z * wdv.z + v.w * wdv.w;
            *(__half2*)(As + r * ASK + kc + i * 4)     = __float22half2_rn(make_float2(v.x, v.y));
            *(__half2*)(As + r * ASK + kc + i * 4 + 2) = __float22half2_rn(make_float2(v.z, v.w));
        }
        s    += __shfl_xor_sync(0xFFFFFFFFu, s, 1);
        s    += __shfl_xor_sync(0xFFFFFFFFu, s, 2);
        dsum += __shfl_xor_sync(0xFFFFFFFFu, dsum, 1);
        dsum += __shfl_xor_sync(0xFFFFFFFFu, dsum, 2);
        if ((tid & 3) == 0 && gr < M) { g_as[gr] = s; g_ad[gr] = dsum; }
    }

    // ---- B staging: transpose [k][n] -> Bs[n][k], fp16 (round-9 measured-good) ----
    {
        int w = tid >> 5, lane = tid & 31;
        int n  = (w & 7) * 32 + lane;        // 0..255
        int k0 = (w >> 3) * 64;              // 0 or 64
        const float* Bp = (n < 128) ? (B0 + n) : (B1 + (n - 128));
        #pragma unroll
        for (int kk = 0; kk < 64; kk += 8) {
            __half2 p0 = __float22half2_rn(make_float2(__ldg(Bp + (size_t)(k0 + kk + 0) * 128),
                                                       __ldg(Bp + (size_t)(k0 + kk + 1) * 128)));
            __half2 p1 = __float22half2_rn(make_float2(__ldg(Bp + (size_t)(k0 + kk + 2) * 128),
                                                       __ldg(Bp + (size_t)(k0 + kk + 3) * 128)));
            __half2 p2 = __float22half2_rn(make_float2(__ldg(Bp + (size_t)(k0 + kk + 4) * 128),
                                                       __ldg(Bp + (size_t)(k0 + kk + 5) * 128)));
            __half2 p3 = __float22half2_rn(make_float2(__ldg(Bp + (size_t)(k0 + kk + 6) * 128),
                                                       __ldg(Bp + (size_t)(k0 + kk + 7) * 128)));
            uint4 u;
            u.x = *(unsigned*)&p0; u.y = *(unsigned*)&p1;
            u.z = *(unsigned*)&p2; u.w = *(unsigned*)&p3;
            *(uint4*)(Bs + n * BSK + k0 + kk) = u;
        }
    }
    __syncthreads();

    // ---- compute: warp tile 32 rows x 64 cols, K=128 via 8 x m16n8k16 ----
    const int w    = tid >> 5;
    const int lane = tid & 31;
    const int grp  = lane >> 2;
    const int tig  = lane & 3;
    const int wr0  = (w & 3) * 32;
    const int wn0  = (w >> 2) * 64;   // 0,64 -> hsrc ; 128,192 -> skip

    uint32_t a_addr[2], b_addr[4];
    {
        int arow = (lane & 15);
        int acol = (lane & 16) ? 8 : 0;
        #pragma unroll
        for (int mt = 0; mt < 2; mt++)
            a_addr[mt] = (uint32_t)__cvta_generic_to_shared(
                As + (wr0 + mt * 16 + arow) * ASK + acol);
        int brow = (lane & 7) + ((lane & 16) ? 8 : 0);
        int bcol = (lane & 8) ? 8 : 0;
        #pragma unroll
        for (int p = 0; p < 4; p++)
            b_addr[p] = (uint32_t)__cvta_generic_to_shared(
                Bs + (wn0 + p * 16 + brow) * BSK + bcol);
    }

    float acc[2][8][4];
    #pragma unroll
    for (int mt = 0; mt < 2; mt++)
        #pragma unroll
        for (int nt = 0; nt < 8; nt++)
            #pragma unroll
            for (int r = 0; r < 4; r++) acc[mt][nt][r] = 0.f;

    #pragma unroll
    for (int ks = 0; ks < 8; ks++) {
        uint32_t koff = ks * 32;   // 16 halves = 32 bytes
        uint32_t a[2][4];
        #pragma unroll
        for (int mt = 0; mt < 2; mt++)
            LDSM4(a[mt][0], a[mt][1], a[mt][2], a[mt][3], a_addr[mt] + koff);
        uint32_t b[8][2];
        #pragma unroll
        for (int p = 0; p < 4; p++)
            LDSM4(b[2 * p][0], b[2 * p][1], b[2 * p + 1][0], b[2 * p + 1][1],
                  b_addr[p] + koff);
        #pragma unroll
        for (int mt = 0; mt < 2; mt++)
            #pragma unroll
            for (int nt = 0; nt < 8; nt++) {
                float* d = acc[mt][nt];
                asm volatile(
                    "mma.sync.aligned.m16n8k16.row.col.f32.f16.f16.f32 "
                    "{%0,%1,%2,%3}, {%4,%5,%6,%7}, {%8,%9}, {%0,%1,%2,%3};"
                    : "+f"(d[0]), "+f"(d[1]), "+f"(d[2]), "+f"(d[3])
                    : "r"(a[mt][0]), "r"(a[mt][1]), "r"(a[mt][2]), "r"(a[mt][3]),
                      "r"(b[nt][0]), "r"(b[nt][1]));
            }
    }

    // ---- epilogue (both halves fp16 now) ----
    const bool to_h = (wn0 < 128);
    __half* outT = to_h ? g_hsrc : g_skip;
    const int cbase = to_h ? 0 : 128;
    #pragma unroll
    for (int mt = 0; mt < 2; mt++) {
        int r_lo = row0 + wr0 + mt * 16 + grp;
        int r_hi = r_lo + 8;
        #pragma unroll
        for (int nt = 0; nt < 8; nt++) {
            int col = wn0 + nt * 8 + 2 * tig - cbase;
            if (r_lo < M)
                *(__half2*)(outT + (size_t)r_lo * 128 + col) =
                    __float22half2_rn(make_float2(acc[mt][nt][0], acc[mt][nt][1]));
            if (r_hi < M)
                *(__half2*)(outT + (size_t)r_hi * 128 + col) =
                    __float22half2_rn(make_float2(acc[mt][nt][2], acc[mt][nt][3]));
        }
    }
}

// ---------------- fused aggregation + epilogue (HALF-WARP per node, clamped MLP-8) ----------------
__global__ __launch_bounds__(256) void agg_kernel(const float* __restrict__ b,
                                                  const float* __restrict__ bl,
                                                  float* __restrict__ out_ext,
                                                  int relu_to_gh, int M) {
    int d = (blockIdx.x * blockDim.x + threadIdx.x) >> 4;
    int l = threadIdx.x & 15;
    if (d >= M) return;

    int o0 = g_off[d], o1 = g_off[d + 1];

    float accA[4] = {0.f, 0.f, 0.f, 0.f};
    float accB[4] = {0.f, 0.f, 0.f, 0.f};
    float Sp = 0.f;
    const __half* __restrict__ H = g_hsrc;

    for (int base = o0; base < o1; base += 8) {
        int   s_[8];
        float e_[8];
        #pragma unroll
        for (int u = 0; u < 8; u++) {
            int jj = base + u;
            bool ok = jj < o1;
            int idx = ok ? jj : o0;
            s_[u] = __ldg(&g_esrc[idx]);
            float ev = __ldg(&g_ex[idx]);
            e_[u] = ok ? ev : 0.f;
        }
        Sp += (e_[0] + e_[1]) + (e_[2] + e_[3]) + (e_[4] + e_[5]) + (e_[6] + e_[7]);
        uint4 u_[8];
        #pragma unroll
        for (int u = 0; u < 8; u++)
            u_[u] = *(const uint4*)(H + (size_t)s_[u] * 128 + l * 8);
        #pragma unroll
        for (int u = 0; u < 8; u++) {
            float2 f0 = __half22float2(*(__half2*)&u_[u].x);
            float2 f1 = __half22float2(*(__half2*)&u_[u].y);
            float2 f2 = __half22float2(*(__half2*)&u_[u].z);
            float2 f3 = __half22float2(*(__half2*)&u_[u].w);
            accA[0] += e_[u] * f0.x; accA[1] += e_[u] * f0.y;
            accA[2] += e_[u] * f1.x; accA[3] += e_[u] * f1.y;
            accB[0] += e_[u] * f2.x; accB[1] += e_[u] * f2.y;
            accB[2] += e_[u] * f3.x; accB[3] += e_[u] * f3.y;
        }
    }

    float inv = 1.f / (Sp + 1e-16f);

    // skip (fp16) + biases
    uint4 sku = *(const uint4*)(g_skip + (size_t)d * 128 + l * 8);
    float2 s0 = __half22float2(*(__half2*)&sku.x);
    float2 s1 = __half22float2(*(__half2*)&sku.y);
    float2 s2 = __half22float2(*(__half2*)&sku.z);
    float2 s3 = __half22float2(*(__half2*)&sku.w);
    float4 b0   = *(const float4*)(b + l * 8);
    float4 b1   = *(const float4*)(b + l * 8 + 4);
    float4 bl0  = *(const float4*)(bl + l * 8);
    float4 bl1  = *(const float4*)(bl + l * 8 + 4);

    float4 oA, oB;
    oA.x = accA[0] * inv + b0.x + s0.x + bl0.x;
    oA.y = accA[1] * inv + b0.y + s0.y + bl0.y;
    oA.z = accA[2] * inv + b0.z + s1.x + bl0.z;
    oA.w = accA[3] * inv + b0.w + s1.y + bl0.w;
    oB.x = accB[0] * inv + b1.x + s2.x + bl1.x;
    oB.y = accB[1] * inv + b1.y + s2.y + bl1.y;
    oB.z = accB[2] * inv + b1.z + s3.x + bl1.z;
    oB.w = accB[3] * inv + b1.w + s3.y + bl1.w;

    if (relu_to_gh) {
        oA.x = fmaxf(oA.x, 0.f); oA.y = fmaxf(oA.y, 0.f);
        oA.z = fmaxf(oA.z, 0.f); oA.w = fmaxf(oA.w, 0.f);
        oB.x = fmaxf(oB.x, 0.f); oB.y = fmaxf(oB.y, 0.f);
        oB.z = fmaxf(oB.z, 0.f); oB.w = fmaxf(oB.w, 0.f);
        *(float4*)(g_h + (size_t)d * 128 + l * 8)     = oA;
        *(float4*)(g_h + (size_t)d * 128 + l * 8 + 4) = oB;
    } else {
        *(float4*)(out_ext + (size_t)d * 128 + l * 8)     = oA;
        *(float4*)(out_ext + (size_t)d * 128 + l * 8 + 4) = oB;
    }
}

// ---------------- launch ----------------
extern "C" void kernel_launch(void* const* d_in, const int* in_sizes, int n_in,
                              void* d_out, int out_size) {
    const float* x   = (const float*)d_in[0];
    const int*   ei  = (const int*)  d_in[1];
    const float* W1s = (const float*)d_in[2];
    const float* W1d = (const float*)d_in[3];
    const float* a1s = (const float*)d_in[4];
    const float* a1d = (const float*)d_in[5];
    const float* b1  = (const float*)d_in[6];
    const float* Wl1 = (const float*)d_in[7];
    const float* bl1 = (const float*)d_in[8];
    const float* W2s = (const float*)d_in[9];
    const float* W2d = (const float*)d_in[10];
    const float* a2s = (const float*)d_in[11];
    const float* a2d = (const float*)d_in[12];
    const float* b2  = (const float*)d_in[13];
    const float* Wl2 = (const float*)d_in[14];
    const float* bl2 = (const float*)d_in[15];

    const int M = in_sizes[0] / CC;        // 50000
    const int E = in_sizes[1] / 2;         // 640000
    const int* src = ei;
    const int* dst = ei + E;

    float *p_h = nullptr, *p_was1 = nullptr, *p_wad1 = nullptr,
          *p_was2 = nullptr, *p_wad2 = nullptr;
    cudaGetSymbolAddress((void**)&p_h,    g_h);     // queries only, capture-safe
    cudaGetSymbolAddress((void**)&p_was1, g_was1);
    cudaGetSymbolAddress((void**)&p_wad1, g_wad1);
    cudaGetSymbolAddress((void**)&p_was2, g_was2);
    cudaGetSymbolAddress((void**)&p_wad2, g_wad2);

    static bool attr_set = false;
    if (!attr_set) {
        cudaFuncSetAttribute(gemm_fused_kernel,
                             cudaFuncAttributeMaxDynamicSharedMemorySize, GSMEM);
        attr_set = true;
    }

    const int nodeBlocks = (M + 255) / 256;
    const int edgeBlocks = (E + 255) / 256;
    const int hwBlocks   = (int)(((long long)M * 16 + 255) / 256);
    const int scanBlocks = (M + SCAN_B - 1) / SCAN_B;
    const int gemmGrid   = (M + 127) / 128;

    combo_zero_kernel<<<nodeBlocks, 256>>>(W1s, a1s, W1d, a1d, W2s, a2s, W2d, a2d, M);  // 1
    hist_kernel<<<edgeBlocks, 256>>>(dst, E);                                           // 2
    scan1_kernel<<<scanBlocks, SCAN_B>>>(M);                                            // 3
    gemm_fused_kernel<<<gemmGrid, 512, GSMEM>>>(x, W1s, Wl1, p_was1, p_wad1, M);        // 4 (ncu window)
    scan2_kernel<<<1, 128>>>(scanBlocks);                                               // 5
    scan3_kernel<<<nodeBlocks, 256>>>(M, E);                                            // 6
    scatter_kernel<<<edgeBlocks, 256>>>(src, dst, E);                                   // 7

    // ---- layer 1 ----
    exf_kernel<<<edgeBlocks, 256>>>(E);                                                 // 8
    agg_kernel<<<hwBlocks, 256>>>(b1, bl1, nullptr, 1, M);                              // 9

    // ---- layer 2 ----
    gemm_fused_kernel<<<gemmGrid, 512, GSMEM>>>(p_h, W2s, Wl2, p_was2, p_wad2, M);      // 10
    exf_kernel<<<edgeBlocks, 256>>>(E);                                                 // 11
    agg_kernel<<<hwBlocks, 256>>>(b2, bl2, (float*)d_out, 0, M);                        // 12
}

// round 14
// speedup vs baseline: 1.1381x; 1.0584x over previous
#include <cuda_runtime.h>
#include <cuda_fp16.h>
#include <cstdint>

#define NN 50000
#define EE 640000
#define CC 128
#define SCAN_B 512

// ---------------- device scratch (no allocations allowed) ----------------
__device__ __half   g_hsrc[NN * CC];   // h_src (fp16 gather table)
__device__ __half   g_skip[NN * CC];   // skip  = in @ Wl (fp16)
__device__ float    g_h   [NN * CC];   // layer-1 output
__device__ float    g_as  [NN];        // alpha_src per node
__device__ float    g_ad  [NN];        // alpha_dst per node
__device__ float    g_was1[CC], g_wad1[CC], g_was2[CC], g_wad2[CC];
// CSR (built once per launch; shared by both layers)
__device__ int      g_deg [NN];
__device__ int      g_off [NN + 1];
__device__ int      g_cur [NN];
__device__ int      g_bsum[128];
__device__ int      g_esrc[EE];        // src ids sorted by dst
__device__ int      g_edst[EE];        // dst ids in same order
__device__ float    g_ex  [EE];        // per-edge exp(logit), CSR order

// ---------------- combo (W@a vectors) + zero_deg merged ----------------
__global__ void combo_zero_kernel(const float* __restrict__ W1s, const float* __restrict__ a1s,
                                  const float* __restrict__ W1d, const float* __restrict__ a1d,
                                  const float* __restrict__ W2s, const float* __restrict__ a2s,
                                  const float* __restrict__ W2d, const float* __restrict__ a2d,
                                  int M) {
    int i = blockIdx.x * blockDim.x + threadIdx.x;
    if (i < M) g_deg[i] = 0;
    if (blockIdx.x == 0 && threadIdx.x < 128) {
        int k = threadIdx.x;
        float s1 = 0.f, d1 = 0.f, s2 = 0.f, d2 = 0.f;
        #pragma unroll 8
        for (int c = 0; c < CC; c++) {
            s1 += W1s[k * CC + c] * a1s[c];
            d1 += W1d[k * CC + c] * a1d[c];
            s2 += W2s[k * CC + c] * a2s[c];
            d2 += W2d[k * CC + c] * a2d[c];
        }
        g_was1[k] = s1; g_wad1[k] = d1; g_was2[k] = s2; g_wad2[k] = d2;
    }
}

// ---------------- CSR build ----------------
__global__ void hist_kernel(const int* __restrict__ dst, int E) {
    int e = blockIdx.x * blockDim.x + threadIdx.x;
    if (e < E) atomicAdd(&g_deg[dst[e]], 1);
}
__global__ __launch_bounds__(SCAN_B) void scan1_kernel(int M) {
    __shared__ int wsum[16];
    int tid = threadIdx.x, lane = tid & 31, wid = tid >> 5;
    int i = blockIdx.x * SCAN_B + tid;
    int v = (i < M) ? g_deg[i] : 0;
    int x = v;
    #pragma unroll
    for (int o = 1; o < 32; o <<= 1) {
        int t = __shfl_up_sync(0xFFFFFFFFu, x, o);
        if (lane >= o) x += t;
    }
    if (lane == 31) wsum[wid] = x;
    __syncthreads();
    if (wid == 0) {
        int s = (lane < 16) ? wsum[lane] : 0;
        #pragma unroll
        for (int o = 1; o < 16; o <<= 1) {
            int t = __shfl_up_sync(0xFFFFFFFFu, s, o);
            if (lane >= o) s += t;
        }
        if (lane < 16) wsum[lane] = s;
    }
    __syncthreads();
    int base = wid ? wsum[wid - 1] : 0;
    int incl = base + x;
    if (i < M) g_off[i] = incl - v;
    if (tid == SCAN_B - 1) g_bsum[blockIdx.x] = incl;
}
__global__ __launch_bounds__(128) void scan2_kernel(int B) {
    __shared__ int sm[128];
    int v = (threadIdx.x < B) ? g_bsum[threadIdx.x] : 0;
    sm[threadIdx.x] = v;
    __syncthreads();
    for (int o = 1; o < 128; o <<= 1) {
        int t = (threadIdx.x >= o) ? sm[threadIdx.x - o] : 0;
        __syncthreads();
        sm[threadIdx.x] += t;
        __syncthreads();
    }
    if (threadIdx.x < B) g_bsum[threadIdx.x] = sm[threadIdx.x] - v;
}
__global__ void scan3_kernel(int M, int E) {
    int i = blockIdx.x * blockDim.x + threadIdx.x;
    if (i < M) {
        int o = g_off[i] + g_bsum[i / SCAN_B];
        g_off[i] = o;
        g_cur[i] = o;
    }
    if (i == 0) g_off[M] = E;
}
__global__ void scatter_kernel(const int* __restrict__ src, const int* __restrict__ dst, int E) {
    int e = blockIdx.x * blockDim.x + threadIdx.x;
    if (e >= E) return;
    int d = dst[e];
    int pos = atomicAdd(&g_cur[d], 1);
    g_esrc[pos] = src[e];
    g_edst[pos] = d;
}

// ---------------- per-edge ex = exp(leaky(as[s]+ad[d])), CSR order, coalesced ----------------
__global__ __launch_bounds__(256) void exf_kernel(int E) {
    int e = blockIdx.x * blockDim.x + threadIdx.x;
    if (e >= E) return;
    int s = g_esrc[e], d = g_edst[e];
    float v = __ldg(&g_as[s]) + __ldg(&g_ad[d]);
    v = v > 0.f ? v : 0.2f * v;   // LeakyReLU(0.2)
    g_ex[e] = __expf(v);
}

// ---------------- fused fp16 tensor-core GEMM (N=256: hsrc | skip) + alpha GEMV ----------------
#define ASK 136
#define BSK 136
#define GSMEM ((128 * ASK + 256 * BSK) * 2 + 256 * 4)

#define LDSM4(r0, r1, r2, r3, addr)                                        \
    asm volatile("ldmatrix.sync.aligned.m8n8.x4.shared.b16 {%0,%1,%2,%3}, [%4];" \
                 : "=r"(r0), "=r"(r1), "=r"(r2), "=r"(r3) : "r"(addr))

__global__ __launch_bounds__(512) void gemm_fused_kernel(const float* __restrict__ A,
                                                         const float* __restrict__ B0,
                                                         const float* __restrict__ B1,
                                                         const float* __restrict__ was,
                                                         const float* __restrict__ wad,
                                                         int M) {
    extern __shared__ __half smh[];
    __half* As = smh;                      // [128][ASK]   (m-major, k contiguous)
    __half* Bs = smh + 128 * ASK;          // [256][BSK]   (n-major, k contiguous)
    float* sWas = (float*)(smh + 128 * ASK + 256 * BSK);
    float* sWad = sWas + 128;

    const int tid  = threadIdx.x;
    const int row0 = blockIdx.x * 128;

    if (tid < 128) { sWas[tid] = was[tid]; sWad[tid] = wad[tid]; }
    __syncthreads();

    // ---- A staging (fp32 -> fp16) + fused fp32 alpha GEMV ----
    {
        int r  = tid >> 2;
        int kc = (tid & 3) * 32;
        int gr = row0 + r;
        float s = 0.f, dsum = 0.f;
        #pragma unroll
        for (int i = 0; i < 8; i++) {
            float4 v = (gr < M) ? *(const float4*)(A + (size_t)gr * 128 + kc + i * 4)
                                : make_float4(0.f, 0.f, 0.f, 0.f);
            float4 wsv = *(const float4*)(sWas + kc + i * 4);
            float4 wdv = *(const float4*)(sWad + kc + i * 4);
            s    += v.x * wsv.x + v.y * wsv.y + v.z * wsv.z + v.w * wsv.w;
            dsum += v.x * wdv.x + v.y * wdv.y + v.z * wdv.z + v.w * wdv.w;
            *(__half2*)(As + r * ASK + kc + i * 4)     = __float22half2_rn(make_float2(v.x, v.y));
            *(__half2*)(As + r * ASK + kc + i * 4 + 2) = __float22half2_rn(make_float2(v.z, v.w));
        }
        s    += __shfl_xor_sync(0xFFFFFFFFu, s, 1);
        s    += __shfl_xor_sync(0xFFFFFFFFu, s, 2);
        dsum += __shfl_xor_sync(0xFFFFFFFFu, dsum, 1);
        dsum += __shfl_xor_sync(0xFFFFFFFFu, dsum, 2);
        if ((tid & 3) == 0 && gr < M) { g_as[gr] = s; g_ad[gr] = dsum; }
    }

    // ---- B staging: transpose [k][n] -> Bs[n][k], fp16 ----
    {
        int w = tid >> 5, lane = tid & 31;
        int n  = (w & 7) * 32 + lane;        // 0..255
        int k0 = (w >> 3) * 64;              // 0 or 64
        const float* Bp = (n < 128) ? (B0 + n) : (B1 + (n - 128));
        #pragma unroll
        for (int kk = 0; kk < 64; kk += 8) {
            __half2 p0 = __float22half2_rn(make_float2(__ldg(Bp + (size_t)(k0 + kk + 0) * 128),
                                                       __ldg(Bp + (size_t)(k0 + kk + 1) * 128)));
            __half2 p1 = __float22half2_rn(make_float2(__ldg(Bp + (size_t)(k0 + kk + 2) * 128),
                                                       __ldg(Bp + (size_t)(k0 + kk + 3) * 128)));
            __half2 p2 = __float22half2_rn(make_float2(__ldg(Bp + (size_t)(k0 + kk + 4) * 128),
                                                       __ldg(Bp + (size_t)(k0 + kk + 5) * 128)));
            __half2 p3 = __float22half2_rn(make_float2(__ldg(Bp + (size_t)(k0 + kk + 6) * 128),
                                                       __ldg(Bp + (size_t)(k0 + kk + 7) * 128)));
            uint4 u;
            u.x = *(unsigned*)&p0; u.y = *(unsigned*)&p1;
            u.z = *(unsigned*)&p2; u.w = *(unsigned*)&p3;
            *(uint4*)(Bs + n * BSK + k0 + kk) = u;
        }
    }
    __syncthreads();

    // ---- compute: warp tile 32 rows x 64 cols, K=128 via 8 x m16n8k16 ----
    const int w    = tid >> 5;
    const int lane = tid & 31;
    const int grp  = lane >> 2;
    const int tig  = lane & 3;
    const int wr0  = (w & 3) * 32;
    const int wn0  = (w >> 2) * 64;   // 0,64 -> hsrc ; 128,192 -> skip

    uint32_t a_addr[2], b_addr[4];
    {
        int arow = (lane & 15);
        int acol = (lane & 16) ? 8 : 0;
        #pragma unroll
        for (int mt = 0; mt < 2; mt++)
            a_addr[mt] = (uint32_t)__cvta_generic_to_shared(
                As + (wr0 + mt * 16 + arow) * ASK + acol);
        int brow = (lane & 7) + ((lane & 16) ? 8 : 0);
        int bcol = (lane & 8) ? 8 : 0;
        #pragma unroll
        for (int p = 0; p < 4; p++)
            b_addr[p] = (uint32_t)__cvta_generic_to_shared(
                Bs + (wn0 + p * 16 + brow) * BSK + bcol);
    }

    float acc[2][8][4];
    #pragma unroll
    for (int mt = 0; mt < 2; mt++)
        #pragma unroll
        for (int nt = 0; nt < 8; nt++)
            #pragma unroll
            for (int r = 0; r < 4; r++) acc[mt][nt][r] = 0.f;

    #pragma unroll
    for (int ks = 0; ks < 8; ks++) {
        uint32_t koff = ks * 32;   // 16 halves = 32 bytes
        uint32_t a[2][4];
        #pragma unroll
        for (int mt = 0; mt < 2; mt++)
            LDSM4(a[mt][0], a[mt][1], a[mt][2], a[mt][3], a_addr[mt] + koff);
        uint32_t b[8][2];
        #pragma unroll
        for (int p = 0; p < 4; p++)
            LDSM4(b[2 * p][0], b[2 * p][1], b[2 * p + 1][0], b[2 * p + 1][1],
                  b_addr[p] + koff);
        #pragma unroll
        for (int mt = 0; mt < 2; mt++)
            #pragma unroll
            for (int nt = 0; nt < 8; nt++) {
                float* d = acc[mt][nt];
                asm volatile(
                    "mma.sync.aligned.m16n8k16.row.col.f32.f16.f16.f32 "
                    "{%0,%1,%2,%3}, {%4,%5,%6,%7}, {%8,%9}, {%0,%1,%2,%3};"
                    : "+f"(d[0]), "+f"(d[1]), "+f"(d[2]), "+f"(d[3])
                    : "r"(a[mt][0]), "r"(a[mt][1]), "r"(a[mt][2]), "r"(a[mt][3]),
                      "r"(b[nt][0]), "r"(b[nt][1]));
            }
    }

    // ---- epilogue (both halves fp16) ----
    const bool to_h = (wn0 < 128);
    __half* outT = to_h ? g_hsrc : g_skip;
    const int cbase = to_h ? 0 : 128;
    #pragma unroll
    for (int mt = 0; mt < 2; mt++) {
        int r_lo = row0 + wr0 + mt * 16 + grp;
        int r_hi = r_lo + 8;
        #pragma unroll
        for (int nt = 0; nt < 8; nt++) {
            int col = wn0 + nt * 8 + 2 * tig - cbase;
            if (r_lo < M)
                *(__half2*)(outT + (size_t)r_lo * 128 + col) =
                    __float22half2_rn(make_float2(acc[mt][nt][0], acc[mt][nt][1]));
            if (r_hi < M)
                *(__half2*)(outT + (size_t)r_hi * 128 + col) =
                    __float22half2_rn(make_float2(acc[mt][nt][2], acc[mt][nt][3]));
        }
    }
}

// ---------------- fused aggregation + epilogue (HALF-WARP per node, clamped MLP-8) ----------------
__global__ __launch_bounds__(256) void agg_kernel(const float* __restrict__ b,
                                                  const float* __restrict__ bl,
                                                  float* __restrict__ out_ext,
                                                  int relu_to_gh, int M) {
    int d = (blockIdx.x * blockDim.x + threadIdx.x) >> 4;
    int l = threadIdx.x & 15;
    if (d >= M) return;

    int o0 = g_off[d], o1 = g_off[d + 1];

    float accA[4] = {0.f, 0.f, 0.f, 0.f};
    float accB[4] = {0.f, 0.f, 0.f, 0.f};
    float Sp = 0.f;
    const __half* __restrict__ H = g_hsrc;

    for (int base = o0; base < o1; base += 8) {
        int   s_[8];
        float e_[8];
        #pragma unroll
        for (int u = 0; u < 8; u++) {
            int jj = base + u;
            bool ok = jj < o1;
            int idx = ok ? jj : o0;
            s_[u] = __ldg(&g_esrc[idx]);
            float ev = __ldg(&g_ex[idx]);
            e_[u] = ok ? ev : 0.f;
        }
        Sp += (e_[0] + e_[1]) + (e_[2] + e_[3]) + (e_[4] + e_[5]) + (e_[6] + e_[7]);
        uint4 u_[8];
        #pragma unroll
        for (int u = 0; u < 8; u++)
            u_[u] = *(const uint4*)(H + (size_t)s_[u] * 128 + l * 8);
        #pragma unroll
        for (int u = 0; u < 8; u++) {
            float2 f0 = __half22float2(*(__half2*)&u_[u].x);
            float2 f1 = __half22float2(*(__half2*)&u_[u].y);
            float2 f2 = __half22float2(*(__half2*)&u_[u].z);
            float2 f3 = __half22float2(*(__half2*)&u_[u].w);
            accA[0] += e_[u] * f0.x; accA[1] += e_[u] * f0.y;
            accA[2] += e_[u] * f1.x; accA[3] += e_[u] * f1.y;
            accB[0] += e_[u] * f2.x; accB[1] += e_[u] * f2.y;
            accB[2] += e_[u] * f3.x; accB[3] += e_[u] * f3.y;
        }
    }

    float inv = 1.f / (Sp + 1e-16f);

    uint4 sku = *(const uint4*)(g_skip + (size_t)d * 128 + l * 8);
    float2 s0 = __half22float2(*(__half2*)&sku.x);
    float2 s1 = __half22float2(*(__half2*)&sku.y);
    float2 s2 = __half22float2(*(__half2*)&sku.z);
    float2 s3 = __half22float2(*(__half2*)&sku.w);
    float4 b0   = *(const float4*)(b + l * 8);
    float4 b1   = *(const float4*)(b + l * 8 + 4);
    float4 bl0  = *(const float4*)(bl + l * 8);
    float4 bl1  = *(const float4*)(bl + l * 8 + 4);

    float4 oA, oB;
    oA.x = accA[0] * inv + b0.x + s0.x + bl0.x;
    oA.y = accA[1] * inv + b0.y + s0.y + bl0.y;
    oA.z = accA[2] * inv + b0.z + s1.x + bl0.z;
    oA.w = accA[3] * inv + b0.w + s1.y + bl0.w;
    oB.x = accB[0] * inv + b1.x + s2.x + bl1.x;
    oB.y = accB[1] * inv + b1.y + s2.y + bl1.y;
    oB.z = accB[2] * inv + b1.z + s3.x + bl1.z;
    oB.w = accB[3] * inv + b1.w + s3.y + bl1.w;

    if (relu_to_gh) {
        oA.x = fmaxf(oA.x, 0.f); oA.y = fmaxf(oA.y, 0.f);
        oA.z = fmaxf(oA.z, 0.f); oA.w = fmaxf(oA.w, 0.f);
        oB.x = fmaxf(oB.x, 0.f); oB.y = fmaxf(oB.y, 0.f);
        oB.z = fmaxf(oB.z, 0.f); oB.w = fmaxf(oB.w, 0.f);
        *(float4*)(g_h + (size_t)d * 128 + l * 8)     = oA;
        *(float4*)(g_h + (size_t)d * 128 + l * 8 + 4) = oB;
    } else {
        *(float4*)(out_ext + (size_t)d * 128 + l * 8)     = oA;
        *(float4*)(out_ext + (size_t)d * 128 + l * 8 + 4) = oB;
    }
}

// ---------------- launch (fork/join: CSR chain overlaps GEMM layer 1) ----------------
extern "C" void kernel_launch(void* const* d_in, const int* in_sizes, int n_in,
                              void* d_out, int out_size) {
    const float* x   = (const float*)d_in[0];
    const int*   ei  = (const int*)  d_in[1];
    const float* W1s = (const float*)d_in[2];
    const float* W1d = (const float*)d_in[3];
    const float* a1s = (const float*)d_in[4];
    const float* a1d = (const float*)d_in[5];
    const float* b1  = (const float*)d_in[6];
    const float* Wl1 = (const float*)d_in[7];
    const float* bl1 = (const float*)d_in[8];
    const float* W2s = (const float*)d_in[9];
    const float* W2d = (const float*)d_in[10];
    const float* a2s = (const float*)d_in[11];
    const float* a2d = (const float*)d_in[12];
    const float* b2  = (const float*)d_in[13];
    const float* Wl2 = (const float*)d_in[14];
    const float* bl2 = (const float*)d_in[15];

    const int M = in_sizes[0] / CC;        // 50000
    const int E = in_sizes[1] / 2;         // 640000
    const int* src = ei;
    const int* dst = ei + E;

    float *p_h = nullptr, *p_was1 = nullptr, *p_wad1 = nullptr,
          *p_was2 = nullptr, *p_wad2 = nullptr;
    cudaGetSymbolAddress((void**)&p_h,    g_h);     // queries only, capture-safe
    cudaGetSymbolAddress((void**)&p_was1, g_was1);
    cudaGetSymbolAddress((void**)&p_wad1, g_wad1);
    cudaGetSymbolAddress((void**)&p_was2, g_was2);
    cudaGetSymbolAddress((void**)&p_wad2, g_wad2);

    static cudaStream_t sB = nullptr;
    static cudaEvent_t evFork = nullptr, evCSR = nullptr;
    static bool init_done = false;
    if (!init_done) {
        cudaFuncSetAttribute(gemm_fused_kernel,
                             cudaFuncAttributeMaxDynamicSharedMemorySize, GSMEM);
        cudaStreamCreateWithFlags(&sB, cudaStreamNonBlocking);
        cudaEventCreateWithFlags(&evFork, cudaEventDisableTiming);
        cudaEventCreateWithFlags(&evCSR, cudaEventDisableTiming);
        init_done = true;
    }

    const int nodeBlocks = (M + 255) / 256;
    const int edgeBlocks = (E + 255) / 256;
    const int hwBlocks   = (int)(((long long)M * 16 + 255) / 256);
    const int scanBlocks = (M + SCAN_B - 1) / SCAN_B;
    const int gemmGrid   = (M + 127) / 128;

    // combo (zeroes deg, computes W@a) — everything depends on it
    combo_zero_kernel<<<nodeBlocks, 256>>>(W1s, a1s, W1d, a1d, W2s, a2s, W2d, a2d, M);

    // fork: CSR chain on side stream, overlapping layer-1 GEMM
    cudaEventRecord(evFork, 0);
    cudaStreamWaitEvent(sB, evFork, 0);
    hist_kernel<<<edgeBlocks, 256, 0, sB>>>(dst, E);
    scan1_kernel<<<scanBlocks, SCAN_B, 0, sB>>>(M);
    scan2_kernel<<<1, 128, 0, sB>>>(scanBlocks);
    scan3_kernel<<<nodeBlocks, 256, 0, sB>>>(M, E);
    scatter_kernel<<<edgeBlocks, 256, 0, sB>>>(src, dst, E);
    cudaEventRecord(evCSR, sB);

    // main stream: layer-1 GEMM runs concurrently with the CSR chain
    gemm_fused_kernel<<<gemmGrid, 512, GSMEM>>>(x, W1s, Wl1, p_was1, p_wad1, M);

    // join: edge pipeline needs both CSR and gemm1 results
    cudaStreamWaitEvent(0, evCSR, 0);

    // ---- layer 1 ----
    exf_kernel<<<edgeBlocks, 256>>>(E);
    agg_kernel<<<hwBlocks, 256>>>(b1, bl1, nullptr, 1, M);

    // ---- layer 2 ----
    gemm_fused_kernel<<<gemmGrid, 512, GSMEM>>>(p_h, W2s, Wl2, p_was2, p_wad2, M);
    exf_kernel<<<edgeBlocks, 256>>>(E);
    agg_kernel<<<hwBlocks, 256>>>(b2, bl2, (float*)d_out, 0, M);
}

// round 15
// speedup vs baseline: 1.1681x; 1.0263x over previous
#include <cuda_runtime.h>
#include <cuda_fp16.h>
#include <cstdint>

#define NN 50000
#define EE 640000
#define CC 128
#define SCAN_B 512

// ---------------- device scratch (no allocations allowed) ----------------
__device__ __half   g_hsrc[NN * CC];   // h_src (fp16 gather table)
__device__ __half   g_skip[NN * CC];   // skip  = in @ Wl (fp16)
__device__ float    g_h   [NN * CC];   // layer-1 output
__device__ float    g_as  [NN];        // alpha_src per node
__device__ float    g_ad  [NN];        // alpha_dst per node
__device__ float    g_was1[CC], g_wad1[CC], g_was2[CC], g_wad2[CC];
// CSR (built once per launch; shared by both layers)
__device__ int      g_deg [NN];
__device__ int      g_off [NN + 1];
__device__ int      g_cur [NN];
__device__ int      g_bsum[128];
__device__ int      g_esrc[EE];        // src ids sorted by dst
__device__ int      g_edst[EE];        // dst ids in same order
__device__ float    g_ex  [EE];        // per-edge exp(logit), CSR order

// ---------------- combo (W@a vectors) + zero_deg merged ----------------
__global__ void combo_zero_kernel(const float* __restrict__ W1s, const float* __restrict__ a1s,
                                  const float* __restrict__ W1d, const float* __restrict__ a1d,
                                  const float* __restrict__ W2s, const float* __restrict__ a2s,
                                  const float* __restrict__ W2d, const float* __restrict__ a2d,
                                  int M) {
    int i = blockIdx.x * blockDim.x + threadIdx.x;
    if (i < M) g_deg[i] = 0;
    if (blockIdx.x == 0 && threadIdx.x < 128) {
        int k = threadIdx.x;
        float s1 = 0.f, d1 = 0.f, s2 = 0.f, d2 = 0.f;
        #pragma unroll 8
        for (int c = 0; c < CC; c++) {
            s1 += W1s[k * CC + c] * a1s[c];
            d1 += W1d[k * CC + c] * a1d[c];
            s2 += W2s[k * CC + c] * a2s[c];
            d2 += W2d[k * CC + c] * a2d[c];
        }
        g_was1[k] = s1; g_wad1[k] = d1; g_was2[k] = s2; g_wad2[k] = d2;
    }
}

// ---------------- CSR build ----------------
__global__ void hist_kernel(const int* __restrict__ dst, int E) {
    int e = blockIdx.x * blockDim.x + threadIdx.x;
    if (e < E) atomicAdd(&g_deg[dst[e]], 1);
}
__global__ __launch_bounds__(SCAN_B) void scan1_kernel(int M) {
    __shared__ int wsum[16];
    int tid = threadIdx.x, lane = tid & 31, wid = tid >> 5;
    int i = blockIdx.x * SCAN_B + tid;
    int v = (i < M) ? g_deg[i] : 0;
    int x = v;
    #pragma unroll
    for (int o = 1; o < 32; o <<= 1) {
        int t = __shfl_up_sync(0xFFFFFFFFu, x, o);
        if (lane >= o) x += t;
    }
    if (lane == 31) wsum[wid] = x;
    __syncthreads();
    if (wid == 0) {
        int s = (lane < 16) ? wsum[lane] : 0;
        #pragma unroll
        for (int o = 1; o < 16; o <<= 1) {
            int t = __shfl_up_sync(0xFFFFFFFFu, s, o);
            if (lane >= o) s += t;
        }
        if (lane < 16) wsum[lane] = s;
    }
    __syncthreads();
    int base = wid ? wsum[wid - 1] : 0;
    int incl = base + x;
    if (i < M) g_off[i] = incl - v;
    if (tid == SCAN_B - 1) g_bsum[blockIdx.x] = incl;
}
__global__ __launch_bounds__(128) void scan2_kernel(int B) {
    __shared__ int sm[128];
    int v = (threadIdx.x < B) ? g_bsum[threadIdx.x] : 0;
    sm[threadIdx.x] = v;
    __syncthreads();
    for (int o = 1; o < 128; o <<= 1) {
        int t = (threadIdx.x >= o) ? sm[threadIdx.x - o] : 0;
        __syncthreads();
        sm[threadIdx.x] += t;
        __syncthreads();
    }
    if (threadIdx.x < B) g_bsum[threadIdx.x] = sm[threadIdx.x] - v;
}
__global__ void scan3_kernel(int M, int E) {
    int i = blockIdx.x * blockDim.x + threadIdx.x;
    if (i < M) {
        int o = g_off[i] + g_bsum[i / SCAN_B];
        g_off[i] = o;
        g_cur[i] = o;
    }
    if (i == 0) g_off[M] = E;
}
__global__ void scatter_kernel(const int* __restrict__ src, const int* __restrict__ dst, int E) {
    int e = blockIdx.x * blockDim.x + threadIdx.x;
    if (e >= E) return;
    int d = dst[e];
    int pos = atomicAdd(&g_cur[d], 1);
    g_esrc[pos] = src[e];
    g_edst[pos] = d;
}

// ---------------- per-edge ex = exp(leaky(as[s]+ad[d])), CSR order, coalesced ----------------
__global__ __launch_bounds__(256) void exf_kernel(int E) {
    int e = blockIdx.x * blockDim.x + threadIdx.x;
    if (e >= E) return;
    int s = g_esrc[e], d = g_edst[e];
    float v = __ldg(&g_as[s]) + __ldg(&g_ad[d]);
    v = v > 0.f ? v : 0.2f * v;   // LeakyReLU(0.2)
    g_ex[e] = __expf(v);
}

// ---------------- fused fp16 tensor-core GEMM (N=256: hsrc | skip) + optional alpha GEMV ----------------
#define ASK 136
#define BSK 136
#define GSMEM ((128 * ASK + 256 * BSK) * 2 + 256 * 4)

#define LDSM4(r0, r1, r2, r3, addr)                                        \
    asm volatile("ldmatrix.sync.aligned.m8n8.x4.shared.b16 {%0,%1,%2,%3}, [%4];" \
                 : "=r"(r0), "=r"(r1), "=r"(r2), "=r"(r3) : "r"(addr))

__global__ __launch_bounds__(512) void gemm_fused_kernel(const float* __restrict__ A,
                                                         const float* __restrict__ B0,
                                                         const float* __restrict__ B1,
                                                         const float* __restrict__ was,
                                                         const float* __restrict__ wad,
                                                         int do_gemv, int M) {
    extern __shared__ __half smh[];
    __half* As = smh;                      // [128][ASK]   (m-major, k contiguous)
    __half* Bs = smh + 128 * ASK;          // [256][BSK]   (n-major, k contiguous)
    float* sWas = (float*)(smh + 128 * ASK + 256 * BSK);
    float* sWad = sWas + 128;

    const int tid  = threadIdx.x;
    const int row0 = blockIdx.x * 128;

    if (do_gemv && tid < 128) { sWas[tid] = was[tid]; sWad[tid] = wad[tid]; }
    __syncthreads();

    // ---- A staging (fp32 -> fp16) + optional fused fp32 alpha GEMV ----
    {
        int r  = tid >> 2;
        int kc = (tid & 3) * 32;
        int gr = row0 + r;
        float s = 0.f, dsum = 0.f;
        #pragma unroll
        for (int i = 0; i < 8; i++) {
            float4 v = (gr < M) ? *(const float4*)(A + (size_t)gr * 128 + kc + i * 4)
                                : make_float4(0.f, 0.f, 0.f, 0.f);
            if (do_gemv) {
                float4 wsv = *(const float4*)(sWas + kc + i * 4);
                float4 wdv = *(const float4*)(sWad + kc + i * 4);
                s    += v.x * wsv.x + v.y * wsv.y + v.z * wsv.z + v.w * wsv.w;
                dsum += v.x * wdv.x + v.y * wdv.y + v.z * wdv.z + v.w * wdv.w;
            }
            *(__half2*)(As + r * ASK + kc + i * 4)     = __float22half2_rn(make_float2(v.x, v.y));
            *(__half2*)(As + r * ASK + kc + i * 4 + 2) = __float22half2_rn(make_float2(v.z, v.w));
        }
        if (do_gemv) {
            s    += __shfl_xor_sync(0xFFFFFFFFu, s, 1);
            s    += __shfl_xor_sync(0xFFFFFFFFu, s, 2);
            dsum += __shfl_xor_sync(0xFFFFFFFFu, dsum, 1);
            dsum += __shfl_xor_sync(0xFFFFFFFFu, dsum, 2);
            if ((tid & 3) == 0 && gr < M) { g_as[gr] = s; g_ad[gr] = dsum; }
        }
    }

    // ---- B staging: transpose [k][n] -> Bs[n][k], fp16 ----
    {
        int w = tid >> 5, lane = tid & 31;
        int n  = (w & 7) * 32 + lane;        // 0..255
        int k0 = (w >> 3) * 64;              // 0 or 64
        const float* Bp = (n < 128) ? (B0 + n) : (B1 + (n - 128));
        #pragma unroll
        for (int kk = 0; kk < 64; kk += 8) {
            __half2 p0 = __float22half2_rn(make_float2(__ldg(Bp + (size_t)(k0 + kk + 0) * 128),
                                                       __ldg(Bp + (size_t)(k0 + kk + 1) * 128)));
            __half2 p1 = __float22half2_rn(make_float2(__ldg(Bp + (size_t)(k0 + kk + 2) * 128),
                                                       __ldg(Bp + (size_t)(k0 + kk + 3) * 128)));
            __half2 p2 = __float22half2_rn(make_float2(__ldg(Bp + (size_t)(k0 + kk + 4) * 128),
                                                       __ldg(Bp + (size_t)(k0 + kk + 5) * 128)));
            __half2 p3 = __float22half2_rn(make_float2(__ldg(Bp + (size_t)(k0 + kk + 6) * 128),
                                                       __ldg(Bp + (size_t)(k0 + kk + 7) * 128)));
            uint4 u;
            u.x = *(unsigned*)&p0; u.y = *(unsigned*)&p1;
            u.z = *(unsigned*)&p2; u.w = *(unsigned*)&p3;
            *(uint4*)(Bs + n * BSK + k0 + kk) = u;
        }
    }
    __syncthreads();

    // ---- compute: warp tile 32 rows x 64 cols, K=128 via 8 x m16n8k16 ----
    const int w    = tid >> 5;
    const int lane = tid & 31;
    const int grp  = lane >> 2;
    const int tig  = lane & 3;
    const int wr0  = (w & 3) * 32;
    const int wn0  = (w >> 2) * 64;   // 0,64 -> hsrc ; 128,192 -> skip

    uint32_t a_addr[2], b_addr[4];
    {
        int arow = (lane & 15);
        int acol = (lane & 16) ? 8 : 0;
        #pragma unroll
        for (int mt = 0; mt < 2; mt++)
            a_addr[mt] = (uint32_t)__cvta_generic_to_shared(
                As + (wr0 + mt * 16 + arow) * ASK + acol);
        int brow = (lane & 7) + ((lane & 16) ? 8 : 0);
        int bcol = (lane & 8) ? 8 : 0;
        #pragma unroll
        for (int p = 0; p < 4; p++)
            b_addr[p] = (uint32_t)__cvta_generic_to_shared(
                Bs + (wn0 + p * 16 + brow) * BSK + bcol);
    }

    float acc[2][8][4];
    #pragma unroll
    for (int mt = 0; mt < 2; mt++)
        #pragma unroll
        for (int nt = 0; nt < 8; nt++)
            #pragma unroll
            for (int r = 0; r < 4; r++) acc[mt][nt][r] = 0.f;

    #pragma unroll
    for (int ks = 0; ks < 8; ks++) {
        uint32_t koff = ks * 32;   // 16 halves = 32 bytes
        uint32_t a[2][4];
        #pragma unroll
        for (int mt = 0; mt < 2; mt++)
            LDSM4(a[mt][0], a[mt][1], a[mt][2], a[mt][3], a_addr[mt] + koff);
        uint32_t b[8][2];
        #pragma unroll
        for (int p = 0; p < 4; p++)
            LDSM4(b[2 * p][0], b[2 * p][1], b[2 * p + 1][0], b[2 * p + 1][1],
                  b_addr[p] + koff);
        #pragma unroll
        for (int mt = 0; mt < 2; mt++)
            #pragma unroll
            for (int nt = 0; nt < 8; nt++) {
                float* d = acc[mt][nt];
                asm volatile(
                    "mma.sync.aligned.m16n8k16.row.col.f32.f16.f16.f32 "
                    "{%0,%1,%2,%3}, {%4,%5,%6,%7}, {%8,%9}, {%0,%1,%2,%3};"
                    : "+f"(d[0]), "+f"(d[1]), "+f"(d[2]), "+f"(d[3])
                    : "r"(a[mt][0]), "r"(a[mt][1]), "r"(a[mt][2]), "r"(a[mt][3]),
                      "r"(b[nt][0]), "r"(b[nt][1]));
            }
    }

    // ---- epilogue (both halves fp16) ----
    const bool to_h = (wn0 < 128);
    __half* outT = to_h ? g_hsrc : g_skip;
    const int cbase = to_h ? 0 : 128;
    #pragma unroll
    for (int mt = 0; mt < 2; mt++) {
        int r_lo = row0 + wr0 + mt * 16 + grp;
        int r_hi = r_lo + 8;
        #pragma unroll
        for (int nt = 0; nt < 8; nt++) {
            int col = wn0 + nt * 8 + 2 * tig - cbase;
            if (r_lo < M)
                *(__half2*)(outT + (size_t)r_lo * 128 + col) =
                    __float22half2_rn(make_float2(acc[mt][nt][0], acc[mt][nt][1]));
            if (r_hi < M)
                *(__half2*)(outT + (size_t)r_hi * 128 + col) =
                    __float22half2_rn(make_float2(acc[mt][nt][2], acc[mt][nt][3]));
        }
    }
}

// ---------------- fused aggregation + epilogue (HALF-WARP per node, clamped MLP-8) ----------------
// relu_to_gh==1 additionally computes next-layer alphas: as2[d]=h[d]@was2, ad2[d]=h[d]@wad2.
__global__ __launch_bounds__(256) void agg_kernel(const float* __restrict__ b,
                                                  const float* __restrict__ bl,
                                                  const float* __restrict__ was2,
                                                  const float* __restrict__ wad2,
                                                  float* __restrict__ out_ext,
                                                  int relu_to_gh, int M) {
    int d = (blockIdx.x * blockDim.x + threadIdx.x) >> 4;
    int l = threadIdx.x & 15;
    if (d >= M) return;

    int o0 = g_off[d], o1 = g_off[d + 1];

    float accA[4] = {0.f, 0.f, 0.f, 0.f};
    float accB[4] = {0.f, 0.f, 0.f, 0.f};
    float Sp = 0.f;
    const __half* __restrict__ H = g_hsrc;

    for (int base = o0; base < o1; base += 8) {
        int   s_[8];
        float e_[8];
        #pragma unroll
        for (int u = 0; u < 8; u++) {
            int jj = base + u;
            bool ok = jj < o1;
            int idx = ok ? jj : o0;
            s_[u] = __ldg(&g_esrc[idx]);
            float ev = __ldg(&g_ex[idx]);
            e_[u] = ok ? ev : 0.f;
        }
        Sp += (e_[0] + e_[1]) + (e_[2] + e_[3]) + (e_[4] + e_[5]) + (e_[6] + e_[7]);
        uint4 u_[8];
        #pragma unroll
        for (int u = 0; u < 8; u++)
            u_[u] = *(const uint4*)(H + (size_t)s_[u] * 128 + l * 8);
        #pragma unroll
        for (int u = 0; u < 8; u++) {
            float2 f0 = __half22float2(*(__half2*)&u_[u].x);
            float2 f1 = __half22float2(*(__half2*)&u_[u].y);
            float2 f2 = __half22float2(*(__half2*)&u_[u].z);
            float2 f3 = __half22float2(*(__half2*)&u_[u].w);
            accA[0] += e_[u] * f0.x; accA[1] += e_[u] * f0.y;
            accA[2] += e_[u] * f1.x; accA[3] += e_[u] * f1.y;
            accB[0] += e_[u] * f2.x; accB[1] += e_[u] * f2.y;
            accB[2] += e_[u] * f3.x; accB[3] += e_[u] * f3.y;
        }
    }

    float inv = 1.f / (Sp + 1e-16f);

    uint4 sku = *(const uint4*)(g_skip + (size_t)d * 128 + l * 8);
    float2 s0 = __half22float2(*(__half2*)&sku.x);
    float2 s1 = __half22float2(*(__half2*)&sku.y);
    float2 s2 = __half22float2(*(__half2*)&sku.z);
    float2 s3 = __half22float2(*(__half2*)&sku.w);
    float4 b0   = *(const float4*)(b + l * 8);
    float4 b1   = *(const float4*)(b + l * 8 + 4);
    float4 bl0  = *(const float4*)(bl + l * 8);
    float4 bl1  = *(const float4*)(bl + l * 8 + 4);

    float4 oA, oB;
    oA.x = accA[0] * inv + b0.x + s0.x + bl0.x;
    oA.y = accA[1] * inv + b0.y + s0.y + bl0.y;
    oA.z = accA[2] * inv + b0.z + s1.x + bl0.z;
    oA.w = accA[3] * inv + b0.w + s1.y + bl0.w;
    oB.x = accB[0] * inv + b1.x + s2.x + bl1.x;
    oB.y = accB[1] * inv + b1.y + s2.y + bl1.y;
    oB.z = accB[2] * inv + b1.z + s3.x + bl1.z;
    oB.w = accB[3] * inv + b1.w + s3.y + bl1.w;

    if (relu_to_gh) {
        oA.x = fmaxf(oA.x, 0.f); oA.y = fmaxf(oA.y, 0.f);
        oA.z = fmaxf(oA.z, 0.f); oA.w = fmaxf(oA.w, 0.f);
        oB.x = fmaxf(oB.x, 0.f); oB.y = fmaxf(oB.y, 0.f);
        oB.z = fmaxf(oB.z, 0.f); oB.w = fmaxf(oB.w, 0.f);
        *(float4*)(g_h + (size_t)d * 128 + l * 8)     = oA;
        *(float4*)(g_h + (size_t)d * 128 + l * 8 + 4) = oB;

        // ---- next-layer alpha GEMV from in-register h ----
        float4 w0 = *(const float4*)(was2 + l * 8);
        float4 w1 = *(const float4*)(was2 + l * 8 + 4);
        float4 v0 = *(const float4*)(wad2 + l * 8);
        float4 v1 = *(const float4*)(wad2 + l * 8 + 4);
        float sa = oA.x * w0.x + oA.y * w0.y + oA.z * w0.z + oA.w * w0.w
                 + oB.x * w1.x + oB.y * w1.y + oB.z * w1.z + oB.w * w1.w;
        float da = oA.x * v0.x + oA.y * v0.y + oA.z * v0.z + oA.w * v0.w
                 + oB.x * v1.x + oB.y * v1.y + oB.z * v1.z + oB.w * v1.w;
        #pragma unroll
        for (int o = 8; o; o >>= 1) {
            sa += __shfl_xor_sync(0xFFFFFFFFu, sa, o);
            da += __shfl_xor_sync(0xFFFFFFFFu, da, o);
        }
        if (l == 0) { g_as[d] = sa; g_ad[d] = da; }
    } else {
        *(float4*)(out_ext + (size_t)d * 128 + l * 8)     = oA;
        *(float4*)(out_ext + (size_t)d * 128 + l * 8 + 4) = oB;
    }
}

// ---------------- launch (two fork/joins) ----------------
extern "C" void kernel_launch(void* const* d_in, const int* in_sizes, int n_in,
                              void* d_out, int out_size) {
    const float* x   = (const float*)d_in[0];
    const int*   ei  = (const int*)  d_in[1];
    const float* W1s = (const float*)d_in[2];
    const float* W1d = (const float*)d_in[3];
    const float* a1s = (const float*)d_in[4];
    const float* a1d = (const float*)d_in[5];
    const float* b1  = (const float*)d_in[6];
    const float* Wl1 = (const float*)d_in[7];
    const float* bl1 = (const float*)d_in[8];
    const float* W2s = (const float*)d_in[9];
    const float* W2d = (const float*)d_in[10];
    const float* a2s = (const float*)d_in[11];
    const float* a2d = (const float*)d_in[12];
    const float* b2  = (const float*)d_in[13];
    const float* Wl2 = (const float*)d_in[14];
    const float* bl2 = (const float*)d_in[15];

    const int M = in_sizes[0] / CC;        // 50000
    const int E = in_sizes[1] / 2;         // 640000
    const int* src = ei;
    const int* dst = ei + E;

    float *p_h = nullptr, *p_was1 = nullptr, *p_wad1 = nullptr,
          *p_was2 = nullptr, *p_wad2 = nullptr;
    cudaGetSymbolAddress((void**)&p_h,    g_h);     // queries only, capture-safe
    cudaGetSymbolAddress((void**)&p_was1, g_was1);
    cudaGetSymbolAddress((void**)&p_wad1, g_wad1);
    cudaGetSymbolAddress((void**)&p_was2, g_was2);
    cudaGetSymbolAddress((void**)&p_wad2, g_wad2);

    static cudaStream_t sB = nullptr;
    static cudaEvent_t evFork = nullptr, evCSR = nullptr, evAgg1 = nullptr, evExf2 = nullptr;
    static bool init_done = false;
    if (!init_done) {
        cudaFuncSetAttribute(gemm_fused_kernel,
                             cudaFuncAttributeMaxDynamicSharedMemorySize, GSMEM);
        cudaStreamCreateWithFlags(&sB, cudaStreamNonBlocking);
        cudaEventCreateWithFlags(&evFork, cudaEventDisableTiming);
        cudaEventCreateWithFlags(&evCSR, cudaEventDisableTiming);
        cudaEventCreateWithFlags(&evAgg1, cudaEventDisableTiming);
        cudaEventCreateWithFlags(&evExf2, cudaEventDisableTiming);
        init_done = true;
    }

    const int nodeBlocks = (M + 255) / 256;
    const int edgeBlocks = (E + 255) / 256;
    const int hwBlocks   = (int)(((long long)M * 16 + 255) / 256);
    const int scanBlocks = (M + SCAN_B - 1) / SCAN_B;
    const int gemmGrid   = (M + 127) / 128;

    // combo (zeroes deg, computes W@a) — everything depends on it
    combo_zero_kernel<<<nodeBlocks, 256>>>(W1s, a1s, W1d, a1d, W2s, a2s, W2d, a2d, M);

    // fork 1: CSR chain on side stream, overlapping layer-1 GEMM
    cudaEventRecord(evFork, 0);
    cudaStreamWaitEvent(sB, evFork, 0);
    hist_kernel<<<edgeBlocks, 256, 0, sB>>>(dst, E);
    scan1_kernel<<<scanBlocks, SCAN_B, 0, sB>>>(M);
    scan2_kernel<<<1, 128, 0, sB>>>(scanBlocks);
    scan3_kernel<<<nodeBlocks, 256, 0, sB>>>(M, E);
    scatter_kernel<<<edgeBlocks, 256, 0, sB>>>(src, dst, E);
    cudaEventRecord(evCSR, sB);

    // main: layer-1 GEMM (with alpha GEMV) concurrent with CSR chain
    gemm_fused_kernel<<<gemmGrid, 512, GSMEM>>>(x, W1s, Wl1, p_was1, p_wad1, 1, M);

    // join 1
    cudaStreamWaitEvent(0, evCSR, 0);

    // ---- layer 1 edge phase (agg1 also emits layer-2 alphas) ----
    exf_kernel<<<edgeBlocks, 256>>>(E);
    agg_kernel<<<hwBlocks, 256>>>(b1, bl1, p_was2, p_wad2, nullptr, 1, M);

    // fork 2: exf2 on side stream (needs only agg1's alphas + CSR), overlapping gemm2
    cudaEventRecord(evAgg1, 0);
    cudaStreamWaitEvent(sB, evAgg1, 0);
    exf_kernel<<<edgeBlocks, 256, 0, sB>>>(E);
    cudaEventRecord(evExf2, sB);

    // main: layer-2 GEMM (no GEMV — alphas already computed by agg1)
    gemm_fused_kernel<<<gemmGrid, 512, GSMEM>>>(p_h, W2s, Wl2, p_was2, p_wad2, 0, M);

    // join 2
    cudaStreamWaitEvent(0, evExf2, 0);

    // ---- layer 2 ----
    agg_kernel<<<hwBlocks, 256>>>(b2, bl2, nullptr, nullptr, (float*)d_out, 0, M);
}